// round 9
// baseline (speedup 1.0000x reference)
#include <cuda_runtime.h>
#include <math_constants.h>
#include <cstdint>

#define S_LEN  2048
#define D_DIM  1024
#define N_H    16
#define M_ROWS 4096

// ------------------------- device scratch (bss) ----------------------------
#define DEVBUF __device__ __align__(256)
DEVBUF float g_hid[M_ROWS * D_DIM];        // tf32-rounded, k-interleaved (16)
DEVBUF float g_wt [4 * D_DIM * D_DIM];     // W^T [n][k], rounded, interleaved
DEVBUF float g_q  [M_ROWS * D_DIM];
DEVBUF float g_k  [M_ROWS * D_DIM];
DEVBUF float g_vt [32 * 64 * S_LEN];       // [bh][d][token], tok-interleaved
DEVBUF float g_ctx[M_ROWS * D_DIM];

// ------------------------------ helpers ------------------------------------
__device__ __forceinline__ uint32_t smem_u32(const void* p) {
    return (uint32_t)__cvta_generic_to_shared(p);
}
__device__ __forceinline__ float rna(float x) {
    uint32_t u; asm("cvt.rna.tf32.f32 %0, %1;" : "=r"(u) : "f"(x));
    return __uint_as_float(u);
}
// 16-wide interleave: physical = (k&3)*4 + (k>>2). A float4 at 4*t4 holds
// logical {t4, t4+4, t4+8, t4+12} -> A/B fragment halves for TWO ksteps.
__device__ __forceinline__ int perm16(int c) { return ((c & 3) << 2) | (c >> 2); }

__device__ __forceinline__ void mma_tf32(float* c, float a0, float a1, float a2,
                                         float a3, float b0, float b1) {
    asm volatile("mma.sync.aligned.m16n8k8.row.col.f32.tf32.tf32.f32 "
                 "{%0,%1,%2,%3}, {%4,%5,%6,%7}, {%8,%9}, {%0,%1,%2,%3};"
                 : "+f"(c[0]), "+f"(c[1]), "+f"(c[2]), "+f"(c[3])
                 : "r"(__float_as_uint(a0)), "r"(__float_as_uint(a1)),
                   "r"(__float_as_uint(a2)), "r"(__float_as_uint(a3)),
                   "r"(__float_as_uint(b0)), "r"(__float_as_uint(b1)));
}
__device__ __forceinline__ void cpa(void* d, const void* s) {
    asm volatile("cp.async.cg.shared.global [%0], [%1], 16;"
                 :: "r"(smem_u32(d)), "l"(s));
}
__device__ __forceinline__ void cp_commit() { asm volatile("cp.async.commit_group;"); }
template<int N> __device__ __forceinline__ void cp_wait() {
    asm volatile("cp.async.wait_group %0;" :: "n"(N));
}

// ---------------------------------------------------------------------------
// prep: round + 16-interleave hidden; transpose+round+interleave W
// ---------------------------------------------------------------------------
__global__ __launch_bounds__(256)
void prep_hid(const float4* __restrict__ in, float4* __restrict__ out, int n16)
{
    int i = blockIdx.x * 256 + threadIdx.x;
    if (i < n16) {
        float s[16], d[16];
        #pragma unroll
        for (int j = 0; j < 4; j++) {
            float4 v = in[i * 4 + j];
            s[j*4] = v.x; s[j*4+1] = v.y; s[j*4+2] = v.z; s[j*4+3] = v.w;
        }
        #pragma unroll
        for (int k = 0; k < 16; k++) d[perm16(k)] = rna(s[k]);
        #pragma unroll
        for (int j = 0; j < 4; j++)
            out[i * 4 + j] = make_float4(d[j*4], d[j*4+1], d[j*4+2], d[j*4+3]);
    }
}

__global__ __launch_bounds__(256)
void prep_w(const float* __restrict__ W0, const float* __restrict__ W1,
            const float* __restrict__ W2, const float* __restrict__ W3,
            float* __restrict__ outbase)
{
    __shared__ float tile[32][33];
    const int z = blockIdx.z;
    const float* W = (z == 0) ? W0 : (z == 1) ? W1 : (z == 2) ? W2 : W3;
    float* out = outbase + (size_t)z * D_DIM * D_DIM;
    const int tx = threadIdx.x, ty = threadIdx.y;
    const int x = blockIdx.x * 32 + tx, y0 = blockIdx.y * 32;
    #pragma unroll
    for (int i = 0; i < 4; i++)
        tile[ty + i * 8][tx] = W[(size_t)(y0 + ty + i * 8) * D_DIM + x];
    __syncthreads();
    #pragma unroll
    for (int i = 0; i < 4; i++) {
        int n = blockIdx.x * 32 + ty + i * 8;
        int k = y0 + tx;
        out[(size_t)n * D_DIM + (k & ~15) + perm16(k & 15)] = rna(tile[tx][ty + i * 8]);
    }
}

// ---------------------------------------------------------------------------
// tf32 projection GEMM. Tiles [128][48]f pitch (192B, phase-conflict-free).
// ---------------------------------------------------------------------------
#define PJ_B     24576
#define PJ_STG   49152
#define PJ_SMEM  (2 * PJ_STG)

__device__ __forceinline__ void proj_load(char* base, const float* Ag,
                                          const float* Bg, int bm, int bn,
                                          int k0, int t)
{
    #pragma unroll
    for (int j = 0; j < 4; j++) {
        int idx = j * 256 + t;
        int r = idx >> 3, c = idx & 7;
        cpa(base + r * 192 + c * 16,        Ag + (size_t)(bm + r) * D_DIM + k0 + c * 4);
        cpa(base + PJ_B + r * 192 + c * 16, Bg + (size_t)(bn + r) * D_DIM + k0 + c * 4);
    }
}

__device__ __forceinline__ void proj_mainloop(const float* Ag, const float* Bg,
                                              char* sm, int bm, int bn, int t,
                                              float acc[4][4][4])
{
    const int lane = t & 31, wid = t >> 5;
    const int wr = wid >> 2, wc = wid & 3;
    const int g = lane >> 2, t4 = lane & 3;

    proj_load(sm, Ag, Bg, bm, bn, 0, t);
    cp_commit();

    for (int c = 0; c < 32; c++) {
        if (c < 31) {
            proj_load(sm + ((c + 1) & 1) * PJ_STG, Ag, Bg, bm, bn, (c + 1) * 32, t);
            cp_commit();
            cp_wait<1>();
        } else {
            cp_wait<0>();
        }
        __syncthreads();
        const float* A = (const float*)(sm + (c & 1) * PJ_STG);
        const float* B = (const float*)(sm + (c & 1) * PJ_STG + PJ_B);
        #pragma unroll
        for (int kg = 0; kg < 2; kg++) {     // two 16-groups per BK=32
            float4 a0[4], a1[4], bb[4];
            #pragma unroll
            for (int mi = 0; mi < 4; mi++) {
                int rb = wr * 64 + mi * 16 + g;
                a0[mi] = *(const float4*)&A[rb * 48 + kg * 16 + t4 * 4];
                a1[mi] = *(const float4*)&A[(rb + 8) * 48 + kg * 16 + t4 * 4];
            }
            #pragma unroll
            for (int nj = 0; nj < 4; nj++) {
                int rb = wc * 32 + nj * 8 + g;
                bb[nj] = *(const float4*)&B[rb * 48 + kg * 16 + t4 * 4];
            }
            #pragma unroll
            for (int mi = 0; mi < 4; mi++)
                #pragma unroll
                for (int nj = 0; nj < 4; nj++) {
                    mma_tf32(acc[mi][nj], a0[mi].x, a1[mi].x, a0[mi].y, a1[mi].y,
                             bb[nj].x, bb[nj].y);
                    mma_tf32(acc[mi][nj], a0[mi].z, a1[mi].z, a0[mi].w, a1[mi].w,
                             bb[nj].z, bb[nj].w);
                }
        }
        __syncthreads();
    }
}

__global__ __launch_bounds__(256, 2)
void proj_qkv(const float* __restrict__ bq, const float* __restrict__ bk,
              const float* __restrict__ bv, const int* __restrict__ stypes,
              const float* __restrict__ sw)
{
    extern __shared__ __align__(16) char sm[];
    const int t = threadIdx.x, lane = t & 31, wid = t >> 5;
    const int wr = wid >> 2, wc = wid & 3;
    const int g = lane >> 2, t4 = lane & 3;
    const int bm = blockIdx.y * 128, bn = blockIdx.x * 128;
    const int z = blockIdx.z;

    const float* bias = (z == 0) ? bq : (z == 1) ? bk : bv;
    const float* Bg = g_wt + (size_t)z * D_DIM * D_DIM;

    float acc[4][4][4] = {};
    proj_mainloop(g_hid, Bg, sm, bm, bn, t, acc);

    // Q gets 0.125 * log2(e) so attention can use exp2
    const float QSCALE = 0.125f * 1.4426950408889634f;
    #pragma unroll
    for (int mi = 0; mi < 4; mi++)
        #pragma unroll
        for (int nj = 0; nj < 4; nj++) {
            int col = bn + wc * 32 + nj * 8 + t4 * 2;
            int cg = col & 15;
            int pp0 = perm16(cg), pp1 = perm16(cg + 1);
            float b0 = bias[col], b1 = bias[col + 1];
            #pragma unroll
            for (int hh = 0; hh < 2; hh++) {
                int row = bm + wr * 64 + mi * 16 + g + hh * 8;
                float s = 1.0f;
                if (z == 0) s = sw[stypes[row] * N_H + (col >> 6)] * QSCALE;
                float x = (acc[mi][nj][hh * 2]     + b0) * s;
                float y = (acc[mi][nj][hh * 2 + 1] + b1) * s;
                if (z < 2) {
                    float* O = (z == 0) ? g_q : g_k;
                    int cb = col & ~15;
                    O[(size_t)row * D_DIM + cb + pp0] = rna(x);
                    O[(size_t)row * D_DIM + cb + pp1] = rna(y);
                } else {
                    int b = row >> 11, tok = row & 2047;
                    int hd = col >> 6, dl = col & 63;
                    int tp = (tok & ~15) + perm16(tok & 15);
                    size_t base = ((size_t)((b << 4) + hd) * 64 + dl) * S_LEN;
                    g_vt[base + tp]         = rna(x);
                    g_vt[base + S_LEN + tp] = rna(y);
                }
            }
        }
}

__global__ __launch_bounds__(256, 2)
void proj_o(const float* __restrict__ bias, float* __restrict__ Cf)
{
    extern __shared__ __align__(16) char sm[];
    const int t = threadIdx.x, lane = t & 31, wid = t >> 5;
    const int wr = wid >> 2, wc = wid & 3;
    const int g = lane >> 2, t4 = lane & 3;
    const int bm = blockIdx.y * 128, bn = blockIdx.x * 128;

    float acc[4][4][4] = {};
    proj_mainloop(g_ctx, g_wt + (size_t)3 * D_DIM * D_DIM, sm, bm, bn, t, acc);

    #pragma unroll
    for (int mi = 0; mi < 4; mi++)
        #pragma unroll
        for (int nj = 0; nj < 4; nj++) {
            int col = bn + wc * 32 + nj * 8 + t4 * 2;
            float b0 = bias[col], b1 = bias[col + 1];
            #pragma unroll
            for (int hh = 0; hh < 2; hh++) {
                int row = bm + wr * 64 + mi * 16 + g + hh * 8;
                float2 o;
                o.x = acc[mi][nj][hh * 2]     + b0;
                o.y = acc[mi][nj][hh * 2 + 1] + b1;
                *(float2*)(Cf + (size_t)row * D_DIM + col) = o;
            }
        }
}

// ---------------------------------------------------------------------------
// flash_tf: fused two-pass flash attention; Q frags in registers; exp2;
// LDS.128 fragments everywhere. 512 threads, 1 CTA/SM.
//   K tiles [128][80]f (pitch 320B), V [64][144]f, Ps [128][144]f.
// ---------------------------------------------------------------------------
#define FL_K    0          // 2 x 40960
#define FL_V    81920      // 36864
#define FL_PS   118784     // 73728 (stages Q [128][80]f at start)
#define FL_IL   192512
#define FL_MS   193024     // int[2][128]
#define FL_RED  194048     // float[4][128]
#define FL_SMEM 196096

__global__ __launch_bounds__(512, 1)
void flash_tf(float* __restrict__ probs, const int* __restrict__ mask)
{
    extern __shared__ __align__(16) char sm[];
    const int t = threadIdx.x, lane = t & 31, wid = t >> 5;
    const int bh = blockIdx.y, b = bh >> 4, h = bh & 15;
    const int q0 = blockIdx.x * 128;
    const int g = lane >> 2, t4 = lane & 3;

    float* Vs   = (float*)(sm + FL_V);
    float* Ps   = (float*)(sm + FL_PS);
    float* il   = (float*)(sm + FL_IL);
    int*   ms   = (int*)(sm + FL_MS);
    float* red  = (float*)(sm + FL_RED);

    const int wr = wid >> 2, wc = wid & 3;     // QK layout: 32q x 32tok strips
    const int wr2 = wid >> 1, wc2 = wid & 1;   // PV layout: 16q x 32d strips

    // preload Q (staged in Ps region, pitch 80f) + K(0) + ms(0)
    #pragma unroll
    for (int j = 0; j < 4; j++) {
        int idx = j * 512 + t;
        int r = idx >> 4, c = idx & 15;
        cpa((char*)Ps + r * 320 + c * 16,
            g_q + (size_t)(b * S_LEN + q0 + r) * D_DIM + h * 64 + c * 4);
    }
    #pragma unroll
    for (int j = 0; j < 4; j++) {
        int idx = j * 512 + t;
        int r = idx >> 4, c = idx & 15;
        cpa(sm + FL_K + r * 320 + c * 16,
            g_k + (size_t)(b * S_LEN + r) * D_DIM + h * 64 + c * 4);
    }
    if (t < 32) cpa((char*)ms + t * 16, mask + b * S_LEN + t * 4);
    cp_commit();
    cp_wait<0>();
    __syncthreads();

    // Q fragments -> registers: 4 kgroups x 2 mi x {row g, row g+8} float4
    float4 qf[4][2][2];
    #pragma unroll
    for (int kg = 0; kg < 4; kg++)
        #pragma unroll
        for (int mi = 0; mi < 2; mi++) {
            int rb = wr * 32 + mi * 16 + g;
            qf[kg][mi][0] = *(const float4*)&Ps[rb * 80 + kg * 16 + t4 * 4];
            qf[kg][mi][1] = *(const float4*)&Ps[(rb + 8) * 80 + kg * 16 + t4 * 4];
        }

    float lp[2][2] = {};

    // =================== pass 1: row sums ===================
    for (int nt = 0; nt < 16; nt++) {
        if (nt > 0) { cp_wait<0>(); __syncthreads(); }
        if (nt < 15) {
            #pragma unroll
            for (int j = 0; j < 4; j++) {
                int idx = j * 512 + t;
                int r = idx >> 4, c = idx & 15;
                cpa(sm + FL_K + ((nt + 1) & 1) * 40960 + r * 320 + c * 16,
                    g_k + (size_t)(b * S_LEN + (nt + 1) * 128 + r) * D_DIM + h * 64 + c * 4);
            }
            if (t < 32) cpa((char*)ms + ((nt + 1) & 1) * 512 + t * 16,
                            mask + b * S_LEN + (nt + 1) * 128 + t * 4);
            cp_commit();
        }

        const float* K = (const float*)(sm + FL_K + (nt & 1) * 40960);

        float acc[2][4][4] = {};
        #pragma unroll
        for (int kg = 0; kg < 4; kg++) {
            float4 bb[4];
            #pragma unroll
            for (int nj = 0; nj < 4; nj++) {
                int rb = wc * 32 + nj * 8 + g;
                bb[nj] = *(const float4*)&K[rb * 80 + kg * 16 + t4 * 4];
            }
            #pragma unroll
            for (int mi = 0; mi < 2; mi++)
                #pragma unroll
                for (int nj = 0; nj < 4; nj++) {
                    mma_tf32(acc[mi][nj], qf[kg][mi][0].x, qf[kg][mi][1].x,
                             qf[kg][mi][0].y, qf[kg][mi][1].y, bb[nj].x, bb[nj].y);
                    mma_tf32(acc[mi][nj], qf[kg][mi][0].z, qf[kg][mi][1].z,
                             qf[kg][mi][0].w, qf[kg][mi][1].w, bb[nj].z, bb[nj].w);
                }
        }

        const int* mcur = ms + (nt & 1) * 128;
        #pragma unroll
        for (int mi = 0; mi < 2; mi++)
            #pragma unroll
            for (int hh = 0; hh < 2; hh++) {
                float s = 0.f;
                #pragma unroll
                for (int nj = 0; nj < 4; nj++) {
                    int cl = wc * 32 + nj * 8 + t4 * 2;
                    float e0 = exp2f(acc[mi][nj][hh * 2]);
                    float e1 = exp2f(acc[mi][nj][hh * 2 + 1]);
                    s += (mcur[cl] ? e0 : 0.f) + (mcur[cl + 1] ? e1 : 0.f);
                }
                s += __shfl_xor_sync(0xffffffffu, s, 1);
                s += __shfl_xor_sync(0xffffffffu, s, 2);
                lp[mi][hh] += s;
            }
    }

    if (t4 == 0)
        #pragma unroll
        for (int mi = 0; mi < 2; mi++)
            #pragma unroll
            for (int hh = 0; hh < 2; hh++)
                red[wc * 128 + wr * 32 + mi * 16 + g + hh * 8] = lp[mi][hh];
    __syncthreads();
    if (t < 128)
        il[t] = 1.f / (red[t] + red[128 + t] + red[256 + t] + red[384 + t]);

    // preload pass 2: K(0)+ms(0) group, V(0) group
    #pragma unroll
    for (int j = 0; j < 4; j++) {
        int idx = j * 512 + t;
        int r = idx >> 4, c = idx & 15;
        cpa(sm + FL_K + r * 320 + c * 16,
            g_k + (size_t)(b * S_LEN + r) * D_DIM + h * 64 + c * 4);
    }
    if (t < 32) cpa((char*)ms + t * 16, mask + b * S_LEN + t * 4);
    cp_commit();
    #pragma unroll
    for (int j = 0; j < 4; j++) {
        int idx = j * 512 + t;
        int r = idx >> 5, c = idx & 31;
        cpa((char*)Vs + r * 576 + c * 16,
            g_vt + ((size_t)bh * 64 + r) * S_LEN + c * 4);
    }
    cp_commit();
    __syncthreads();                           // il visible to all

    // =================== pass 2: emit probs + PV ===================
    float accPV[4][4] = {};
    float* Pg = probs + ((size_t)bh * S_LEN + q0) * S_LEN;

    for (int nt = 0; nt < 16; nt++) {
        if (nt < 15) {
            #pragma unroll
            for (int j = 0; j < 4; j++) {
                int idx = j * 512 + t;
                int r = idx >> 4, c = idx & 15;
                cpa(sm + FL_K + ((nt + 1) & 1) * 40960 + r * 320 + c * 16,
                    g_k + (size_t)(b * S_LEN + (nt + 1) * 128 + r) * D_DIM + h * 64 + c * 4);
            }
            if (t < 32) cpa((char*)ms + ((nt + 1) & 1) * 512 + t * 16,
                            mask + b * S_LEN + (nt + 1) * 128 + t * 4);
            cp_commit();
            cp_wait<2>();    // K(nt) ready
        } else {
            cp_wait<1>();    // K(15) ready; V(15) may remain
        }
        __syncthreads();

        const float* K = (const float*)(sm + FL_K + (nt & 1) * 40960);

        // ---- QK (A-frags from registers) ----
        float acc[2][4][4] = {};
        #pragma unroll
        for (int kg = 0; kg < 4; kg++) {
            float4 bb[4];
            #pragma unroll
            for (int nj = 0; nj < 4; nj++) {
                int rb = wc * 32 + nj * 8 + g;
                bb[nj] = *(const float4*)&K[rb * 80 + kg * 16 + t4 * 4];
            }
            #pragma unroll
            for (int mi = 0; mi < 2; mi++)
                #pragma unroll
                for (int nj = 0; nj < 4; nj++) {
                    mma_tf32(acc[mi][nj], qf[kg][mi][0].x, qf[kg][mi][1].x,
                             qf[kg][mi][0].y, qf[kg][mi][1].y, bb[nj].x, bb[nj].y);
                    mma_tf32(acc[mi][nj], qf[kg][mi][0].z, qf[kg][mi][1].z,
                             qf[kg][mi][0].w, qf[kg][mi][1].w, bb[nj].z, bb[nj].w);
                }
        }

        // ---- p = exp2(s) * il, write to probs + Ps (perm16) ----
        const int* mcur = ms + (nt & 1) * 128;
        #pragma unroll
        for (int mi = 0; mi < 2; mi++)
            #pragma unroll
            for (int hh = 0; hh < 2; hh++) {
                int r = wr * 32 + mi * 16 + g + hh * 8;
                float iv = il[r];
                #pragma unroll
                for (int nj = 0; nj < 4; nj++) {
                    int cl = wc * 32 + nj * 8 + t4 * 2;
                    int cg = cl & 15;
                    float p0 = (mcur[cl]     ? exp2f(acc[mi][nj][hh * 2])     * iv : 0.f);
                    float p1 = (mcur[cl + 1] ? exp2f(acc[mi][nj][hh * 2 + 1]) * iv : 0.f);
                    float2 o; o.x = p0; o.y = p1;
                    *(float2*)(Pg + (size_t)r * S_LEN + nt * 128 + cl) = o;
                    int gb = r * 144 + (cl & ~15);
                    Ps[gb + perm16(cg)]     = rna(p0);
                    Ps[gb + perm16(cg + 1)] = rna(p1);
                }
            }

        if (nt < 15) cp_wait<1>();   // V(nt) ready, K(nt+1) stays in flight
        else         cp_wait<0>();
        __syncthreads();

        // ---- PV (LDS.128 frags) ----
        #pragma unroll
        for (int kg = 0; kg < 8; kg++) {
            float4 a0, a1, bb[4];
            int rb = wr2 * 16 + g;
            a0 = *(const float4*)&Ps[rb * 144 + kg * 16 + t4 * 4];
            a1 = *(const float4*)&Ps[(rb + 8) * 144 + kg * 16 + t4 * 4];
            #pragma unroll
            for (int nj = 0; nj < 4; nj++) {
                int vb = wc2 * 32 + nj * 8 + g;
                bb[nj] = *(const float4*)&Vs[vb * 144 + kg * 16 + t4 * 4];
            }
            #pragma unroll
            for (int nj = 0; nj < 4; nj++) {
                mma_tf32(accPV[nj], a0.x, a1.x, a0.y, a1.y, bb[nj].x, bb[nj].y);
                mma_tf32(accPV[nj], a0.z, a1.z, a0.w, a1.w, bb[nj].z, bb[nj].w);
            }
        }
        __syncthreads();   // Ps + Vs free

        if (nt < 15) {
            #pragma unroll
            for (int j = 0; j < 4; j++) {
                int idx = j * 512 + t;
                int r = idx >> 5, c = idx & 31;
                cpa((char*)Vs + r * 576 + c * 16,
                    g_vt + ((size_t)bh * 64 + r) * S_LEN + (nt + 1) * 128 + c * 4);
            }
            cp_commit();
        }
    }

    // ---- ctx write (perm16-interleaved) ----
    #pragma unroll
    for (int nj = 0; nj < 4; nj++) {
        int col = h * 64 + wc2 * 32 + nj * 8 + t4 * 2;
        int cg = col & 15;
        int cb = col & ~15;
        #pragma unroll
        for (int hh = 0; hh < 2; hh++) {
            int row = b * S_LEN + q0 + wr2 * 16 + g + hh * 8;
            g_ctx[(size_t)row * D_DIM + cb + perm16(cg)]     = rna(accPV[nj][hh * 2]);
            g_ctx[(size_t)row * D_DIM + cb + perm16(cg + 1)] = rna(accPV[nj][hh * 2 + 1]);
        }
    }
}

// ---------------------------------------------------------------------------
extern "C" void kernel_launch(void* const* d_in, const int* in_sizes, int n_in,
                              void* d_out, int out_size)
{
    (void)in_sizes; (void)n_in; (void)out_size;

    const float* hidden = (const float*)d_in[0];
    const int*   mask   = (const int*)  d_in[1];
    const int*   stypes = (const int*)  d_in[2];
    const float* Wq = (const float*)d_in[3];
    const float* bq = (const float*)d_in[4];
    const float* Wk = (const float*)d_in[5];
    const float* bk = (const float*)d_in[6];
    const float* Wv = (const float*)d_in[7];
    const float* bv = (const float*)d_in[8];
    const float* Wo = (const float*)d_in[9];
    const float* bo = (const float*)d_in[10];
    const float* sw = (const float*)d_in[11];

    float* out   = (float*)d_out;
    float* probs = out + (size_t)M_ROWS * D_DIM;

    float *hidp, *wtp;
    cudaGetSymbolAddress((void**)&hidp, g_hid);
    cudaGetSymbolAddress((void**)&wtp,  g_wt);

    cudaFuncSetAttribute(proj_qkv, cudaFuncAttributeMaxDynamicSharedMemorySize, PJ_SMEM);
    cudaFuncSetAttribute(proj_o,   cudaFuncAttributeMaxDynamicSharedMemorySize, PJ_SMEM);
    cudaFuncSetAttribute(flash_tf, cudaFuncAttributeMaxDynamicSharedMemorySize, FL_SMEM);

    prep_hid<<<1024, 256>>>((const float4*)hidden, (float4*)hidp, 262144);
    prep_w<<<dim3(32, 32, 4), dim3(32, 8)>>>(Wq, Wk, Wv, Wo, wtp);

    proj_qkv<<<dim3(8, 32, 3), 256, PJ_SMEM>>>(bq, bk, bv, stypes, sw);

    flash_tf<<<dim3(16, 32), 512, FL_SMEM>>>(probs, mask);

    proj_o<<<dim3(8, 32), 256, PJ_SMEM>>>(bo, out);
}

// round 10
// speedup vs baseline: 1.0637x; 1.0637x over previous
#include <cuda_runtime.h>
#include <math_constants.h>
#include <cstdint>

#define S_LEN  2048
#define D_DIM  1024
#define N_H    16
#define M_ROWS 4096

// ------------------------- device scratch (bss) ----------------------------
#define DEVBUF __device__ __align__(256)
DEVBUF float g_hid[M_ROWS * D_DIM];        // tf32-rounded, k-interleaved (8)
DEVBUF float g_wt [4 * D_DIM * D_DIM];     // W^T [n][k], rounded, interleaved
DEVBUF float g_q  [M_ROWS * D_DIM];
DEVBUF float g_k  [M_ROWS * D_DIM];
DEVBUF float g_vt [32 * 64 * S_LEN];       // [bh][d][token], tok-interleaved
DEVBUF float g_ctx[M_ROWS * D_DIM];

// ------------------------------ helpers ------------------------------------
__device__ __forceinline__ uint32_t smem_u32(const void* p) {
    return (uint32_t)__cvta_generic_to_shared(p);
}
__device__ __forceinline__ float rna(float x) {
    uint32_t u; asm("cvt.rna.tf32.f32 %0, %1;" : "=r"(u) : "f"(x));
    return __uint_as_float(u);
}
__device__ __forceinline__ int perm8(int c) { return ((c & 3) << 1) | (c >> 2); }

__device__ __forceinline__ void mma_tf32(float* c, float a0, float a1, float a2,
                                         float a3, float b0, float b1) {
    asm volatile("mma.sync.aligned.m16n8k8.row.col.f32.tf32.tf32.f32 "
                 "{%0,%1,%2,%3}, {%4,%5,%6,%7}, {%8,%9}, {%0,%1,%2,%3};"
                 : "+f"(c[0]), "+f"(c[1]), "+f"(c[2]), "+f"(c[3])
                 : "r"(__float_as_uint(a0)), "r"(__float_as_uint(a1)),
                   "r"(__float_as_uint(a2)), "r"(__float_as_uint(a3)),
                   "r"(__float_as_uint(b0)), "r"(__float_as_uint(b1)));
}
__device__ __forceinline__ void cpa(void* d, const void* s) {
    asm volatile("cp.async.cg.shared.global [%0], [%1], 16;"
                 :: "r"(smem_u32(d)), "l"(s));
}
__device__ __forceinline__ void cp_commit() { asm volatile("cp.async.commit_group;"); }
template<int N> __device__ __forceinline__ void cp_wait() {
    asm volatile("cp.async.wait_group %0;" :: "n"(N));
}

// ---------------------------------------------------------------------------
// prep: round + 8-interleave hidden; transpose+round+interleave W
// ---------------------------------------------------------------------------
__global__ __launch_bounds__(256)
void prep_hid(const float4* __restrict__ in, float4* __restrict__ out, int ng)
{
    int i = blockIdx.x * 256 + threadIdx.x;
    if (i < ng) {
        float4 v0 = in[i * 2], v1 = in[i * 2 + 1];
        float s[8] = {v0.x, v0.y, v0.z, v0.w, v1.x, v1.y, v1.z, v1.w};
        float d[8];
        #pragma unroll
        for (int k = 0; k < 8; k++) d[perm8(k)] = rna(s[k]);
        out[i * 2]     = make_float4(d[0], d[1], d[2], d[3]);
        out[i * 2 + 1] = make_float4(d[4], d[5], d[6], d[7]);
    }
}

__global__ __launch_bounds__(256)
void prep_w(const float* __restrict__ W0, const float* __restrict__ W1,
            const float* __restrict__ W2, const float* __restrict__ W3,
            float* __restrict__ outbase)
{
    __shared__ float tile[32][33];
    const int z = blockIdx.z;
    const float* W = (z == 0) ? W0 : (z == 1) ? W1 : (z == 2) ? W2 : W3;
    float* out = outbase + (size_t)z * D_DIM * D_DIM;
    const int tx = threadIdx.x, ty = threadIdx.y;
    const int x = blockIdx.x * 32 + tx, y0 = blockIdx.y * 32;
    #pragma unroll
    for (int i = 0; i < 4; i++)
        tile[ty + i * 8][tx] = W[(size_t)(y0 + ty + i * 8) * D_DIM + x];
    __syncthreads();
    #pragma unroll
    for (int i = 0; i < 4; i++) {
        int n = blockIdx.x * 32 + ty + i * 8;
        int k = y0 + tx;
        out[(size_t)n * D_DIM + (k & ~7) + perm8(k & 7)] = rna(tile[tx][ty + i * 8]);
    }
}

// ---------------------------------------------------------------------------
// tf32 projection GEMM (R8 structure: [128][40]f tiles, LDS.64 fragments)
// ---------------------------------------------------------------------------
#define PJ_STG   40960
#define PJ_SMEM  (2 * PJ_STG)

__device__ __forceinline__ void proj_load(char* base, const float* Ag,
                                          const float* Bg, int bm, int bn,
                                          int k0, int t)
{
    #pragma unroll
    for (int j = 0; j < 4; j++) {
        int idx = j * 256 + t;
        int r = idx >> 3, c = idx & 7;
        cpa(base + r * 160 + c * 16,         Ag + (size_t)(bm + r) * D_DIM + k0 + c * 4);
        cpa(base + 20480 + r * 160 + c * 16, Bg + (size_t)(bn + r) * D_DIM + k0 + c * 4);
    }
}

__device__ __forceinline__ void proj_mainloop(const float* Ag, const float* Bg,
                                              char* sm, int bm, int bn, int t,
                                              float acc[4][4][4])
{
    const int lane = t & 31, wid = t >> 5;
    const int wr = wid >> 2, wc = wid & 3;
    const int g = lane >> 2, t4 = lane & 3;

    proj_load(sm, Ag, Bg, bm, bn, 0, t);
    cp_commit();

    for (int c = 0; c < 32; c++) {
        if (c < 31) {
            proj_load(sm + ((c + 1) & 1) * PJ_STG, Ag, Bg, bm, bn, (c + 1) * 32, t);
            cp_commit();
            cp_wait<1>();
        } else {
            cp_wait<0>();
        }
        __syncthreads();
        const float* A = (const float*)(sm + (c & 1) * PJ_STG);
        const float* B = (const float*)(sm + (c & 1) * PJ_STG + 20480);
        #pragma unroll
        for (int ks = 0; ks < 4; ks++) {
            float2 a0[4], a1[4], bb[4];
            #pragma unroll
            for (int mi = 0; mi < 4; mi++) {
                int rb = wr * 64 + mi * 16 + g;
                a0[mi] = *(const float2*)&A[rb * 40 + ks * 8 + t4 * 2];
                a1[mi] = *(const float2*)&A[(rb + 8) * 40 + ks * 8 + t4 * 2];
            }
            #pragma unroll
            for (int nj = 0; nj < 4; nj++) {
                int rb = wc * 32 + nj * 8 + g;
                bb[nj] = *(const float2*)&B[rb * 40 + ks * 8 + t4 * 2];
            }
            #pragma unroll
            for (int mi = 0; mi < 4; mi++)
                #pragma unroll
                for (int nj = 0; nj < 4; nj++)
                    mma_tf32(acc[mi][nj], a0[mi].x, a1[mi].x, a0[mi].y, a1[mi].y,
                             bb[nj].x, bb[nj].y);
        }
        __syncthreads();
    }
}

__global__ __launch_bounds__(256, 2)
void proj_qkv(const float* __restrict__ bq, const float* __restrict__ bk,
              const float* __restrict__ bv, const int* __restrict__ stypes,
              const float* __restrict__ sw)
{
    extern __shared__ __align__(16) char sm[];
    const int t = threadIdx.x, lane = t & 31, wid = t >> 5;
    const int wr = wid >> 2, wc = wid & 3;
    const int g = lane >> 2, t4 = lane & 3;
    const int bm = blockIdx.y * 128, bn = blockIdx.x * 128;
    const int z = blockIdx.z;

    const float* bias = (z == 0) ? bq : (z == 1) ? bk : bv;
    const float* Bg = g_wt + (size_t)z * D_DIM * D_DIM;

    float acc[4][4][4] = {};
    proj_mainloop(g_hid, Bg, sm, bm, bn, t, acc);

    // Q gets 0.125 * log2(e) so attention can use exp2
    const float QSCALE = 0.125f * 1.4426950408889634f;
    const int p0 = perm8(2 * t4), p1 = perm8(2 * t4 + 1);
    #pragma unroll
    for (int mi = 0; mi < 4; mi++)
        #pragma unroll
        for (int nj = 0; nj < 4; nj++) {
            int col = bn + wc * 32 + nj * 8 + t4 * 2;
            float b0 = bias[col], b1 = bias[col + 1];
            #pragma unroll
            for (int hh = 0; hh < 2; hh++) {
                int row = bm + wr * 64 + mi * 16 + g + hh * 8;
                float s = 1.0f;
                if (z == 0) s = sw[stypes[row] * N_H + (col >> 6)] * QSCALE;
                float x = (acc[mi][nj][hh * 2]     + b0) * s;
                float y = (acc[mi][nj][hh * 2 + 1] + b1) * s;
                if (z < 2) {
                    float* O = (z == 0) ? g_q : g_k;
                    int cb = col & ~7;
                    O[(size_t)row * D_DIM + cb + p0] = rna(x);
                    O[(size_t)row * D_DIM + cb + p1] = rna(y);
                } else {
                    int b = row >> 11, tok = row & 2047;
                    int hd = col >> 6, dl = col & 63;
                    int tp = (tok & ~7) + perm8(tok & 7);
                    size_t base = ((size_t)((b << 4) + hd) * 64 + dl) * S_LEN;
                    g_vt[base + tp]         = rna(x);
                    g_vt[base + S_LEN + tp] = rna(y);
                }
            }
        }
}

__global__ __launch_bounds__(256, 2)
void proj_o(const float* __restrict__ bias, float* __restrict__ Cf)
{
    extern __shared__ __align__(16) char sm[];
    const int t = threadIdx.x, lane = t & 31, wid = t >> 5;
    const int wr = wid >> 2, wc = wid & 3;
    const int g = lane >> 2, t4 = lane & 3;
    const int bm = blockIdx.y * 128, bn = blockIdx.x * 128;

    float acc[4][4][4] = {};
    proj_mainloop(g_ctx, g_wt + (size_t)3 * D_DIM * D_DIM, sm, bm, bn, t, acc);

    #pragma unroll
    for (int mi = 0; mi < 4; mi++)
        #pragma unroll
        for (int nj = 0; nj < 4; nj++) {
            int col = bn + wc * 32 + nj * 8 + t4 * 2;
            float b0 = bias[col], b1 = bias[col + 1];
            #pragma unroll
            for (int hh = 0; hh < 2; hh++) {
                int row = bm + wr * 64 + mi * 16 + g + hh * 8;
                float2 o;
                o.x = acc[mi][nj][hh * 2]     + b0;
                o.y = acc[mi][nj][hh * 2 + 1] + b1;
                *(float2*)(Cf + (size_t)row * D_DIM + col) = o;
            }
        }
}

// ---------------------------------------------------------------------------
// flash_tf: fused two-pass flash attention (R8 layouts); Q frags in registers;
// exp2; pass 2 with DOUBLE-BUFFERED V and full-tile prefetch (2 syncs/tile,
// no exposed waits). 512 threads, 1 CTA/SM.
// ---------------------------------------------------------------------------
#define FL_K    0          // 2 x [128][72]f = 73728
#define FL_V    73728      // 2 x [64][136]f = 69632
#define FL_PS   143360     // [128][136]f    = 69632 (stages Q [128][72]f)
#define FL_IL   212992     // float[128]
#define FL_MS   213504     // int[2][128]
#define FL_RED  214528     // float[4][128]
#define FL_SMEM 216576

__global__ __launch_bounds__(512, 1)
void flash_tf(float* __restrict__ probs, const int* __restrict__ mask)
{
    extern __shared__ __align__(16) char sm[];
    const int t = threadIdx.x, lane = t & 31, wid = t >> 5;
    const int bh = blockIdx.y, b = bh >> 4, h = bh & 15;
    const int q0 = blockIdx.x * 128;
    const int g = lane >> 2, t4 = lane & 3;

    float* Ps   = (float*)(sm + FL_PS);
    float* il   = (float*)(sm + FL_IL);
    int*   ms   = (int*)(sm + FL_MS);
    float* red  = (float*)(sm + FL_RED);

    const int wr = wid >> 2, wc = wid & 3;     // QK layout: 32q x 32tok strips
    const int wr2 = wid >> 1, wc2 = wid & 1;   // PV layout: 16q x 32d strips

    // preload Q (staged in Ps region, pitch 72f) + K(0) + ms(0)
    #pragma unroll
    for (int j = 0; j < 4; j++) {
        int idx = j * 512 + t;
        int r = idx >> 4, c = idx & 15;
        cpa((char*)Ps + r * 288 + c * 16,
            g_q + (size_t)(b * S_LEN + q0 + r) * D_DIM + h * 64 + c * 4);
    }
    #pragma unroll
    for (int j = 0; j < 4; j++) {
        int idx = j * 512 + t;
        int r = idx >> 4, c = idx & 15;
        cpa(sm + FL_K + r * 288 + c * 16,
            g_k + (size_t)(b * S_LEN + r) * D_DIM + h * 64 + c * 4);
    }
    if (t < 32) cpa((char*)ms + t * 16, mask + b * S_LEN + t * 4);
    cp_commit();
    cp_wait<0>();
    __syncthreads();

    // Q fragments -> registers (shared across all tiles + both passes)
    float2 qf[8][2][2];
    #pragma unroll
    for (int ks = 0; ks < 8; ks++)
        #pragma unroll
        for (int mi = 0; mi < 2; mi++) {
            int rb = wr * 32 + mi * 16 + g;
            qf[ks][mi][0] = *(const float2*)&Ps[rb * 72 + ks * 8 + t4 * 2];
            qf[ks][mi][1] = *(const float2*)&Ps[(rb + 8) * 72 + ks * 8 + t4 * 2];
        }

    float lp[2][2] = {};

    // =================== pass 1: row sums ===================
    for (int nt = 0; nt < 16; nt++) {
        if (nt > 0) { cp_wait<0>(); __syncthreads(); }
        if (nt < 15) {
            #pragma unroll
            for (int j = 0; j < 4; j++) {
                int idx = j * 512 + t;
                int r = idx >> 4, c = idx & 15;
                cpa(sm + FL_K + ((nt + 1) & 1) * 36864 + r * 288 + c * 16,
                    g_k + (size_t)(b * S_LEN + (nt + 1) * 128 + r) * D_DIM + h * 64 + c * 4);
            }
            if (t < 32) cpa((char*)ms + ((nt + 1) & 1) * 512 + t * 16,
                            mask + b * S_LEN + (nt + 1) * 128 + t * 4);
            cp_commit();
        }

        const float* K = (const float*)(sm + FL_K + (nt & 1) * 36864);

        float acc[2][4][4] = {};
        #pragma unroll
        for (int ks = 0; ks < 8; ks++) {
            float2 bb[4];
            #pragma unroll
            for (int nj = 0; nj < 4; nj++) {
                int rb = wc * 32 + nj * 8 + g;
                bb[nj] = *(const float2*)&K[rb * 72 + ks * 8 + t4 * 2];
            }
            #pragma unroll
            for (int mi = 0; mi < 2; mi++)
                #pragma unroll
                for (int nj = 0; nj < 4; nj++)
                    mma_tf32(acc[mi][nj], qf[ks][mi][0].x, qf[ks][mi][1].x,
                             qf[ks][mi][0].y, qf[ks][mi][1].y, bb[nj].x, bb[nj].y);
        }

        const int* mcur = ms + (nt & 1) * 128;
        #pragma unroll
        for (int mi = 0; mi < 2; mi++)
            #pragma unroll
            for (int hh = 0; hh < 2; hh++) {
                float s = 0.f;
                #pragma unroll
                for (int nj = 0; nj < 4; nj++) {
                    int cl = wc * 32 + nj * 8 + t4 * 2;
                    float e0 = exp2f(acc[mi][nj][hh * 2]);
                    float e1 = exp2f(acc[mi][nj][hh * 2 + 1]);
                    s += (mcur[cl] ? e0 : 0.f) + (mcur[cl + 1] ? e1 : 0.f);
                }
                s += __shfl_xor_sync(0xffffffffu, s, 1);
                s += __shfl_xor_sync(0xffffffffu, s, 2);
                lp[mi][hh] += s;
            }
    }

    if (t4 == 0)
        #pragma unroll
        for (int mi = 0; mi < 2; mi++)
            #pragma unroll
            for (int hh = 0; hh < 2; hh++)
                red[wc * 128 + wr * 32 + mi * 16 + g + hh * 8] = lp[mi][hh];
    __syncthreads();
    if (t < 128)
        il[t] = 1.f / (red[t] + red[128 + t] + red[256 + t] + red[384 + t]);

    // preload pass 2: ONE group = K(0) + ms(0) + V(0)
    #pragma unroll
    for (int j = 0; j < 4; j++) {
        int idx = j * 512 + t;
        int r = idx >> 4, c = idx & 15;
        cpa(sm + FL_K + r * 288 + c * 16,
            g_k + (size_t)(b * S_LEN + r) * D_DIM + h * 64 + c * 4);
    }
    if (t < 32) cpa((char*)ms + t * 16, mask + b * S_LEN + t * 4);
    #pragma unroll
    for (int j = 0; j < 4; j++) {
        int idx = j * 512 + t;
        int r = idx >> 5, c = idx & 31;
        cpa(sm + FL_V + r * 544 + c * 16,
            g_vt + ((size_t)bh * 64 + r) * S_LEN + c * 4);
    }
    cp_commit();

    // =================== pass 2: emit probs + PV ===================
    float accPV[4][4] = {};
    float* Pg = probs + ((size_t)bh * S_LEN + q0) * S_LEN;
    const int pp0 = perm8(2 * t4), pp1 = perm8(2 * t4 + 1);

    for (int nt = 0; nt < 16; nt++) {
        cp_wait<0>();        // K(nt)+V(nt)+ms(nt) arrived (prefetched a full tile ago)
        __syncthreads();     // + all warps done with prev PV (Ps/K/V buffers free)

        // prefetch next tile: full-tile latency budget
        if (nt < 15) {
            #pragma unroll
            for (int j = 0; j < 4; j++) {
                int idx = j * 512 + t;
                int r = idx >> 4, c = idx & 15;
                cpa(sm + FL_K + ((nt + 1) & 1) * 36864 + r * 288 + c * 16,
                    g_k + (size_t)(b * S_LEN + (nt + 1) * 128 + r) * D_DIM + h * 64 + c * 4);
            }
            if (t < 32) cpa((char*)ms + ((nt + 1) & 1) * 512 + t * 16,
                            mask + b * S_LEN + (nt + 1) * 128 + t * 4);
            #pragma unroll
            for (int j = 0; j < 4; j++) {
                int idx = j * 512 + t;
                int r = idx >> 5, c = idx & 31;
                cpa(sm + FL_V + ((nt + 1) & 1) * 34816 + r * 544 + c * 16,
                    g_vt + ((size_t)bh * 64 + r) * S_LEN + (nt + 1) * 128 + c * 4);
            }
            cp_commit();
        }

        const float* K  = (const float*)(sm + FL_K + (nt & 1) * 36864);
        const float* Vc = (const float*)(sm + FL_V + (nt & 1) * 34816);

        // ---- QK (A-frags from registers) ----
        float acc[2][4][4] = {};
        #pragma unroll
        for (int ks = 0; ks < 8; ks++) {
            float2 bb[4];
            #pragma unroll
            for (int nj = 0; nj < 4; nj++) {
                int rb = wc * 32 + nj * 8 + g;
                bb[nj] = *(const float2*)&K[rb * 72 + ks * 8 + t4 * 2];
            }
            #pragma unroll
            for (int mi = 0; mi < 2; mi++)
                #pragma unroll
                for (int nj = 0; nj < 4; nj++)
                    mma_tf32(acc[mi][nj], qf[ks][mi][0].x, qf[ks][mi][1].x,
                             qf[ks][mi][0].y, qf[ks][mi][1].y, bb[nj].x, bb[nj].y);
        }

        // ---- p = exp2(s) * il, write to probs + Ps ----
        const int* mcur = ms + (nt & 1) * 128;
        #pragma unroll
        for (int mi = 0; mi < 2; mi++)
            #pragma unroll
            for (int hh = 0; hh < 2; hh++) {
                int r = wr * 32 + mi * 16 + g + hh * 8;
                float iv = il[r];
                #pragma unroll
                for (int nj = 0; nj < 4; nj++) {
                    int cl = wc * 32 + nj * 8 + t4 * 2;
                    float p0 = (mcur[cl]     ? exp2f(acc[mi][nj][hh * 2])     * iv : 0.f);
                    float p1 = (mcur[cl + 1] ? exp2f(acc[mi][nj][hh * 2 + 1]) * iv : 0.f);
                    float2 o; o.x = p0; o.y = p1;
                    *(float2*)(Pg + (size_t)r * S_LEN + nt * 128 + cl) = o;
                    int gb = r * 136 + (cl & ~7);
                    Ps[gb + pp0] = rna(p0);
                    Ps[gb + pp1] = rna(p1);
                }
            }

        __syncthreads();     // Ps visible; V(nt) already resident

        // ---- PV ----
        #pragma unroll
        for (int ks = 0; ks < 16; ks++) {
            float2 a0, a1, bb[4];
            int rb = wr2 * 16 + g;
            a0 = *(const float2*)&Ps[rb * 136 + ks * 8 + t4 * 2];
            a1 = *(const float2*)&Ps[(rb + 8) * 136 + ks * 8 + t4 * 2];
            #pragma unroll
            for (int nj = 0; nj < 4; nj++) {
                int vb = wc2 * 32 + nj * 8 + g;
                bb[nj] = *(const float2*)&Vc[vb * 136 + ks * 8 + t4 * 2];
            }
            #pragma unroll
            for (int nj = 0; nj < 4; nj++)
                mma_tf32(accPV[nj], a0.x, a1.x, a0.y, a1.y, bb[nj].x, bb[nj].y);
        }
        // no trailing sync: next tile's top sync protects buffer reuse
    }

    // ---- ctx write (perm8-interleaved) ----
    #pragma unroll
    for (int nj = 0; nj < 4; nj++) {
        int col = h * 64 + wc2 * 32 + nj * 8 + t4 * 2;
        int cb = col & ~7;
        #pragma unroll
        for (int hh = 0; hh < 2; hh++) {
            int row = b * S_LEN + q0 + wr2 * 16 + g + hh * 8;
            g_ctx[(size_t)row * D_DIM + cb + pp0] = rna(accPV[nj][hh * 2]);
            g_ctx[(size_t)row * D_DIM + cb + pp1] = rna(accPV[nj][hh * 2 + 1]);
        }
    }
}

// ---------------------------------------------------------------------------
extern "C" void kernel_launch(void* const* d_in, const int* in_sizes, int n_in,
                              void* d_out, int out_size)
{
    (void)in_sizes; (void)n_in; (void)out_size;

    const float* hidden = (const float*)d_in[0];
    const int*   mask   = (const int*)  d_in[1];
    const int*   stypes = (const int*)  d_in[2];
    const float* Wq = (const float*)d_in[3];
    const float* bq = (const float*)d_in[4];
    const float* Wk = (const float*)d_in[5];
    const float* bk = (const float*)d_in[6];
    const float* Wv = (const float*)d_in[7];
    const float* bv = (const float*)d_in[8];
    const float* Wo = (const float*)d_in[9];
    const float* bo = (const float*)d_in[10];
    const float* sw = (const float*)d_in[11];

    float* out   = (float*)d_out;
    float* probs = out + (size_t)M_ROWS * D_DIM;

    float *hidp, *wtp;
    cudaGetSymbolAddress((void**)&hidp, g_hid);
    cudaGetSymbolAddress((void**)&wtp,  g_wt);

    cudaFuncSetAttribute(proj_qkv, cudaFuncAttributeMaxDynamicSharedMemorySize, PJ_SMEM);
    cudaFuncSetAttribute(proj_o,   cudaFuncAttributeMaxDynamicSharedMemorySize, PJ_SMEM);
    cudaFuncSetAttribute(flash_tf, cudaFuncAttributeMaxDynamicSharedMemorySize, FL_SMEM);

    prep_hid<<<2048, 256>>>((const float4*)hidden, (float4*)hidp, 524288);
    prep_w<<<dim3(32, 32, 4), dim3(32, 8)>>>(Wq, Wk, Wv, Wo, wtp);

    proj_qkv<<<dim3(8, 32, 3), 256, PJ_SMEM>>>(bq, bk, bv, stypes, sw);

    flash_tf<<<dim3(16, 32), 512, FL_SMEM>>>(probs, mask);

    proj_o<<<dim3(8, 32), 256, PJ_SMEM>>>(bo, out);
}

// round 11
// speedup vs baseline: 1.0943x; 1.0288x over previous
#include <cuda_runtime.h>
#include <math_constants.h>
#include <cstdint>

#define S_LEN  2048
#define D_DIM  1024
#define N_H    16
#define M_ROWS 4096

// ------------------------- device scratch (bss) ----------------------------
#define DEVBUF __device__ __align__(256)
DEVBUF float g_hid[M_ROWS * D_DIM];        // tf32-rounded, k-interleaved (8)
DEVBUF float g_wt [4 * D_DIM * D_DIM];     // W^T [n][k], rounded, interleaved
DEVBUF float g_q  [M_ROWS * D_DIM];
DEVBUF float g_k  [M_ROWS * D_DIM];
DEVBUF float g_vt [32 * 64 * S_LEN];       // [bh][d][token], tok-interleaved
DEVBUF float g_ctx[M_ROWS * D_DIM];
DEVBUF float g_mbias[2 * S_LEN];           // mask ? 0 : -1e30

// ------------------------------ helpers ------------------------------------
__device__ __forceinline__ uint32_t smem_u32(const void* p) {
    return (uint32_t)__cvta_generic_to_shared(p);
}
__device__ __forceinline__ float rna(float x) {
    uint32_t u; asm("cvt.rna.tf32.f32 %0, %1;" : "=r"(u) : "f"(x));
    return __uint_as_float(u);
}
__device__ __forceinline__ int perm8(int c) { return ((c & 3) << 1) | (c >> 2); }

__device__ __forceinline__ void mma_tf32(float* c, float a0, float a1, float a2,
                                         float a3, float b0, float b1) {
    asm volatile("mma.sync.aligned.m16n8k8.row.col.f32.tf32.tf32.f32 "
                 "{%0,%1,%2,%3}, {%4,%5,%6,%7}, {%8,%9}, {%0,%1,%2,%3};"
                 : "+f"(c[0]), "+f"(c[1]), "+f"(c[2]), "+f"(c[3])
                 : "r"(__float_as_uint(a0)), "r"(__float_as_uint(a1)),
                   "r"(__float_as_uint(a2)), "r"(__float_as_uint(a3)),
                   "r"(__float_as_uint(b0)), "r"(__float_as_uint(b1)));
}
__device__ __forceinline__ void cpa(void* d, const void* s) {
    asm volatile("cp.async.cg.shared.global [%0], [%1], 16;"
                 :: "r"(smem_u32(d)), "l"(s));
}
__device__ __forceinline__ void cp_commit() { asm volatile("cp.async.commit_group;"); }
template<int N> __device__ __forceinline__ void cp_wait() {
    asm volatile("cp.async.wait_group %0;" :: "n"(N));
}

// ---------------------------------------------------------------------------
// prep: round + 8-interleave hidden + mask bias; transpose+round+interleave W
// ---------------------------------------------------------------------------
__global__ __launch_bounds__(256)
void prep_hid(const float4* __restrict__ in, float4* __restrict__ out, int ng,
              const int* __restrict__ mask, float* __restrict__ mbias, int nb)
{
    int i = blockIdx.x * 256 + threadIdx.x;
    if (i < ng) {
        float4 v0 = in[i * 2], v1 = in[i * 2 + 1];
        float s[8] = {v0.x, v0.y, v0.z, v0.w, v1.x, v1.y, v1.z, v1.w};
        float d[8];
        #pragma unroll
        for (int k = 0; k < 8; k++) d[perm8(k)] = rna(s[k]);
        out[i * 2]     = make_float4(d[0], d[1], d[2], d[3]);
        out[i * 2 + 1] = make_float4(d[4], d[5], d[6], d[7]);
    }
    int j = i - ng;
    if (j >= 0 && j < nb) mbias[j] = mask[j] ? 0.f : -1e30f;
}

__global__ __launch_bounds__(256)
void prep_w(const float* __restrict__ W0, const float* __restrict__ W1,
            const float* __restrict__ W2, const float* __restrict__ W3,
            float* __restrict__ outbase)
{
    __shared__ float tile[32][33];
    const int z = blockIdx.z;
    const float* W = (z == 0) ? W0 : (z == 1) ? W1 : (z == 2) ? W2 : W3;
    float* out = outbase + (size_t)z * D_DIM * D_DIM;
    const int tx = threadIdx.x, ty = threadIdx.y;
    const int x = blockIdx.x * 32 + tx, y0 = blockIdx.y * 32;
    #pragma unroll
    for (int i = 0; i < 4; i++)
        tile[ty + i * 8][tx] = W[(size_t)(y0 + ty + i * 8) * D_DIM + x];
    __syncthreads();
    #pragma unroll
    for (int i = 0; i < 4; i++) {
        int n = blockIdx.x * 32 + ty + i * 8;
        int k = y0 + tx;
        out[(size_t)n * D_DIM + (k & ~7) + perm8(k & 7)] = rna(tile[tx][ty + i * 8]);
    }
}

// ---------------------------------------------------------------------------
// tf32 projection GEMM (unchanged from R10)
// ---------------------------------------------------------------------------
#define PJ_STG   40960
#define PJ_SMEM  (2 * PJ_STG)

__device__ __forceinline__ void proj_load(char* base, const float* Ag,
                                          const float* Bg, int bm, int bn,
                                          int k0, int t)
{
    #pragma unroll
    for (int j = 0; j < 4; j++) {
        int idx = j * 256 + t;
        int r = idx >> 3, c = idx & 7;
        cpa(base + r * 160 + c * 16,         Ag + (size_t)(bm + r) * D_DIM + k0 + c * 4);
        cpa(base + 20480 + r * 160 + c * 16, Bg + (size_t)(bn + r) * D_DIM + k0 + c * 4);
    }
}

__device__ __forceinline__ void proj_mainloop(const float* Ag, const float* Bg,
                                              char* sm, int bm, int bn, int t,
                                              float acc[4][4][4])
{
    const int lane = t & 31, wid = t >> 5;
    const int wr = wid >> 2, wc = wid & 3;
    const int g = lane >> 2, t4 = lane & 3;

    proj_load(sm, Ag, Bg, bm, bn, 0, t);
    cp_commit();

    for (int c = 0; c < 32; c++) {
        if (c < 31) {
            proj_load(sm + ((c + 1) & 1) * PJ_STG, Ag, Bg, bm, bn, (c + 1) * 32, t);
            cp_commit();
            cp_wait<1>();
        } else {
            cp_wait<0>();
        }
        __syncthreads();
        const float* A = (const float*)(sm + (c & 1) * PJ_STG);
        const float* B = (const float*)(sm + (c & 1) * PJ_STG + 20480);
        #pragma unroll
        for (int ks = 0; ks < 4; ks++) {
            float2 a0[4], a1[4], bb[4];
            #pragma unroll
            for (int mi = 0; mi < 4; mi++) {
                int rb = wr * 64 + mi * 16 + g;
                a0[mi] = *(const float2*)&A[rb * 40 + ks * 8 + t4 * 2];
                a1[mi] = *(const float2*)&A[(rb + 8) * 40 + ks * 8 + t4 * 2];
            }
            #pragma unroll
            for (int nj = 0; nj < 4; nj++) {
                int rb = wc * 32 + nj * 8 + g;
                bb[nj] = *(const float2*)&B[rb * 40 + ks * 8 + t4 * 2];
            }
            #pragma unroll
            for (int mi = 0; mi < 4; mi++)
                #pragma unroll
                for (int nj = 0; nj < 4; nj++)
                    mma_tf32(acc[mi][nj], a0[mi].x, a1[mi].x, a0[mi].y, a1[mi].y,
                             bb[nj].x, bb[nj].y);
        }
        __syncthreads();
    }
}

__global__ __launch_bounds__(256, 2)
void proj_qkv(const float* __restrict__ bq, const float* __restrict__ bk,
              const float* __restrict__ bv, const int* __restrict__ stypes,
              const float* __restrict__ sw)
{
    extern __shared__ __align__(16) char sm[];
    const int t = threadIdx.x, lane = t & 31, wid = t >> 5;
    const int wr = wid >> 2, wc = wid & 3;
    const int g = lane >> 2, t4 = lane & 3;
    const int bm = blockIdx.y * 128, bn = blockIdx.x * 128;
    const int z = blockIdx.z;

    const float* bias = (z == 0) ? bq : (z == 1) ? bk : bv;
    const float* Bg = g_wt + (size_t)z * D_DIM * D_DIM;

    float acc[4][4][4] = {};
    proj_mainloop(g_hid, Bg, sm, bm, bn, t, acc);

    // Q gets 0.125 * log2(e) so attention can use exp2
    const float QSCALE = 0.125f * 1.4426950408889634f;
    const int p0 = perm8(2 * t4), p1 = perm8(2 * t4 + 1);
    #pragma unroll
    for (int mi = 0; mi < 4; mi++)
        #pragma unroll
        for (int nj = 0; nj < 4; nj++) {
            int col = bn + wc * 32 + nj * 8 + t4 * 2;
            float b0 = bias[col], b1 = bias[col + 1];
            #pragma unroll
            for (int hh = 0; hh < 2; hh++) {
                int row = bm + wr * 64 + mi * 16 + g + hh * 8;
                float s = 1.0f;
                if (z == 0) s = sw[stypes[row] * N_H + (col >> 6)] * QSCALE;
                float x = (acc[mi][nj][hh * 2]     + b0) * s;
                float y = (acc[mi][nj][hh * 2 + 1] + b1) * s;
                if (z < 2) {
                    float* O = (z == 0) ? g_q : g_k;
                    int cb = col & ~7;
                    O[(size_t)row * D_DIM + cb + p0] = rna(x);
                    O[(size_t)row * D_DIM + cb + p1] = rna(y);
                } else {
                    int b = row >> 11, tok = row & 2047;
                    int hd = col >> 6, dl = col & 63;
                    int tp = (tok & ~7) + perm8(tok & 7);
                    size_t base = ((size_t)((b << 4) + hd) * 64 + dl) * S_LEN;
                    g_vt[base + tp]         = rna(x);
                    g_vt[base + S_LEN + tp] = rna(y);
                }
            }
        }
}

__global__ __launch_bounds__(256, 2)
void proj_o(const float* __restrict__ bias, float* __restrict__ Cf)
{
    extern __shared__ __align__(16) char sm[];
    const int t = threadIdx.x, lane = t & 31, wid = t >> 5;
    const int wr = wid >> 2, wc = wid & 3;
    const int g = lane >> 2, t4 = lane & 3;
    const int bm = blockIdx.y * 128, bn = blockIdx.x * 128;

    float acc[4][4][4] = {};
    proj_mainloop(g_ctx, g_wt + (size_t)3 * D_DIM * D_DIM, sm, bm, bn, t, acc);

    #pragma unroll
    for (int mi = 0; mi < 4; mi++)
        #pragma unroll
        for (int nj = 0; nj < 4; nj++) {
            int col = bn + wc * 32 + nj * 8 + t4 * 2;
            float b0 = bias[col], b1 = bias[col + 1];
            #pragma unroll
            for (int hh = 0; hh < 2; hh++) {
                int row = bm + wr * 64 + mi * 16 + g + hh * 8;
                float2 o;
                o.x = acc[mi][nj][hh * 2]     + b0;
                o.y = acc[mi][nj][hh * 2 + 1] + b1;
                *(float2*)(Cf + (size_t)row * D_DIM + col) = o;
            }
        }
}

// ---------------------------------------------------------------------------
// flash_tf: fused two-pass flash attention.
//  - mask folded as additive float bias into the MMA accumulator init
//  - pass 2 folds log2(1/l) into the accumulator too: p = exp2(acc), bare
//  - pass 1: K triple-buffered (3rd buffer = idle V region), prefetch depth 2
//  - pass 2: K+V double-buffered, full-tile prefetch (as R10)
// 512 threads, 1 CTA/SM.
// ---------------------------------------------------------------------------
#define FL_K    0          // 2 x [128][72]f = 73728 (pass1 also uses FL_V as buf2)
#define FL_V    73728      // 2 x [64][136]f = 69632
#define FL_PS   143360     // [128][136]f    = 69632 (stages Q [128][72]f)
#define FL_IL   212992     // float[128]  (log2(1/l))
#define FL_MB   213504     // float[3][128] mask bias
#define FL_RED  215040     // float[4][128]
#define FL_SMEM 217088

__global__ __launch_bounds__(512, 1)
void flash_tf(float* __restrict__ probs)
{
    extern __shared__ __align__(16) char sm[];
    const int t = threadIdx.x, lane = t & 31, wid = t >> 5;
    const int bh = blockIdx.y, b = bh >> 4, h = bh & 15;
    const int q0 = blockIdx.x * 128;
    const int g = lane >> 2, t4 = lane & 3;

    float* Ps   = (float*)(sm + FL_PS);
    float* il   = (float*)(sm + FL_IL);
    float* mb   = (float*)(sm + FL_MB);
    float* red  = (float*)(sm + FL_RED);

    const int wr = wid >> 2, wc = wid & 3;     // QK layout: 32q x 32tok strips
    const int wr2 = wid >> 1, wc2 = wid & 1;   // PV layout: 16q x 32d strips

    const float* mbg = g_mbias + b * S_LEN;

    // pass-1 K buffer addresses (triple buffer: buf2 lives in the V region)
    auto kb1 = [&](int i) -> char* {
        return sm + (i == 2 ? FL_V : FL_K + i * 36864);
    };

    // preload group A: Q (staged in Ps) + K(0) + mb(0)
    #pragma unroll
    for (int j = 0; j < 4; j++) {
        int idx = j * 512 + t;
        int r = idx >> 4, c = idx & 15;
        cpa((char*)Ps + r * 288 + c * 16,
            g_q + (size_t)(b * S_LEN + q0 + r) * D_DIM + h * 64 + c * 4);
    }
    #pragma unroll
    for (int j = 0; j < 4; j++) {
        int idx = j * 512 + t;
        int r = idx >> 4, c = idx & 15;
        cpa(kb1(0) + r * 288 + c * 16,
            g_k + (size_t)(b * S_LEN + r) * D_DIM + h * 64 + c * 4);
    }
    if (t < 32) cpa((char*)mb + t * 16, mbg + t * 4);
    cp_commit();
    // preload group B: K(1) + mb(1)
    #pragma unroll
    for (int j = 0; j < 4; j++) {
        int idx = j * 512 + t;
        int r = idx >> 4, c = idx & 15;
        cpa(kb1(1) + r * 288 + c * 16,
            g_k + (size_t)(b * S_LEN + 128 + r) * D_DIM + h * 64 + c * 4);
    }
    if (t < 32) cpa((char*)mb + 512 + t * 16, mbg + 128 + t * 4);
    cp_commit();

    cp_wait<1>();          // Q + K(0) ready
    __syncthreads();

    // Q fragments -> registers (shared across all tiles + both passes)
    float2 qf[8][2][2];
    #pragma unroll
    for (int ks = 0; ks < 8; ks++)
        #pragma unroll
        for (int mi = 0; mi < 2; mi++) {
            int rb = wr * 32 + mi * 16 + g;
            qf[ks][mi][0] = *(const float2*)&Ps[rb * 72 + ks * 8 + t4 * 2];
            qf[ks][mi][1] = *(const float2*)&Ps[(rb + 8) * 72 + ks * 8 + t4 * 2];
        }

    float lp[2][2] = {};

    // =================== pass 1: row sums (depth-2 K pipeline) ===============
    for (int nt = 0; nt < 16; nt++) {
        if (nt > 0) {
            if (nt < 15) cp_wait<1>(); else cp_wait<0>();
            __syncthreads();
        }
        if (nt + 2 <= 15) {
            int dst = (nt + 2) % 3;
            #pragma unroll
            for (int j = 0; j < 4; j++) {
                int idx = j * 512 + t;
                int r = idx >> 4, c = idx & 15;
                cpa(kb1(dst) + r * 288 + c * 16,
                    g_k + (size_t)(b * S_LEN + (nt + 2) * 128 + r) * D_DIM + h * 64 + c * 4);
            }
            if (t < 32) cpa((char*)mb + dst * 512 + t * 16, mbg + (nt + 2) * 128 + t * 4);
            cp_commit();
        }

        const float* K = (const float*)kb1(nt % 3);
        const float* mbc = mb + (nt % 3) * 128;

        // acc initialized with mask bias (free masking)
        float acc[2][4][4];
        #pragma unroll
        for (int nj = 0; nj < 4; nj++) {
            int cl = wc * 32 + nj * 8 + t4 * 2;
            float m0 = mbc[cl], m1 = mbc[cl + 1];
            #pragma unroll
            for (int mi = 0; mi < 2; mi++) {
                acc[mi][nj][0] = m0; acc[mi][nj][1] = m1;
                acc[mi][nj][2] = m0; acc[mi][nj][3] = m1;
            }
        }
        #pragma unroll
        for (int ks = 0; ks < 8; ks++) {
            float2 bb[4];
            #pragma unroll
            for (int nj = 0; nj < 4; nj++) {
                int rb = wc * 32 + nj * 8 + g;
                bb[nj] = *(const float2*)&K[rb * 72 + ks * 8 + t4 * 2];
            }
            #pragma unroll
            for (int mi = 0; mi < 2; mi++)
                #pragma unroll
                for (int nj = 0; nj < 4; nj++)
                    mma_tf32(acc[mi][nj], qf[ks][mi][0].x, qf[ks][mi][1].x,
                             qf[ks][mi][0].y, qf[ks][mi][1].y, bb[nj].x, bb[nj].y);
        }

        #pragma unroll
        for (int mi = 0; mi < 2; mi++)
            #pragma unroll
            for (int hh = 0; hh < 2; hh++) {
                float s = 0.f;
                #pragma unroll
                for (int nj = 0; nj < 4; nj++)
                    s += exp2f(acc[mi][nj][hh * 2]) + exp2f(acc[mi][nj][hh * 2 + 1]);
                s += __shfl_xor_sync(0xffffffffu, s, 1);
                s += __shfl_xor_sync(0xffffffffu, s, 2);
                lp[mi][hh] += s;
            }
    }

    if (t4 == 0)
        #pragma unroll
        for (int mi = 0; mi < 2; mi++)
            #pragma unroll
            for (int hh = 0; hh < 2; hh++)
                red[wc * 128 + wr * 32 + mi * 16 + g + hh * 8] = lp[mi][hh];
    __syncthreads();       // red visible AND all pass-1 K-buffer reads done
    if (t < 128)
        il[t] = -__log2f(red[t] + red[128 + t] + red[256 + t] + red[384 + t]);

    // preload pass 2: ONE group = K(0) + mb(0) + V(0)  (safe: post-sync)
    #pragma unroll
    for (int j = 0; j < 4; j++) {
        int idx = j * 512 + t;
        int r = idx >> 4, c = idx & 15;
        cpa(sm + FL_K + r * 288 + c * 16,
            g_k + (size_t)(b * S_LEN + r) * D_DIM + h * 64 + c * 4);
    }
    if (t < 32) cpa((char*)mb + t * 16, mbg + t * 4);
    #pragma unroll
    for (int j = 0; j < 4; j++) {
        int idx = j * 512 + t;
        int r = idx >> 5, c = idx & 31;
        cpa(sm + FL_V + r * 544 + c * 16,
            g_vt + ((size_t)bh * 64 + r) * S_LEN + c * 4);
    }
    cp_commit();

    // =================== pass 2: emit probs + PV ===================
    float accPV[4][4] = {};
    float* Pg = probs + ((size_t)bh * S_LEN + q0) * S_LEN;
    const int pp0 = perm8(2 * t4), pp1 = perm8(2 * t4 + 1);

    for (int nt = 0; nt < 16; nt++) {
        cp_wait<0>();        // K(nt)+V(nt)+mb(nt) arrived
        __syncthreads();     // + all warps done with prev PV (buffers free; il visible)

        if (nt < 15) {
            #pragma unroll
            for (int j = 0; j < 4; j++) {
                int idx = j * 512 + t;
                int r = idx >> 4, c = idx & 15;
                cpa(sm + FL_K + ((nt + 1) & 1) * 36864 + r * 288 + c * 16,
                    g_k + (size_t)(b * S_LEN + (nt + 1) * 128 + r) * D_DIM + h * 64 + c * 4);
            }
            if (t < 32) cpa((char*)mb + ((nt + 1) & 1) * 512 + t * 16,
                            mbg + (nt + 1) * 128 + t * 4);
            #pragma unroll
            for (int j = 0; j < 4; j++) {
                int idx = j * 512 + t;
                int r = idx >> 5, c = idx & 31;
                cpa(sm + FL_V + ((nt + 1) & 1) * 34816 + r * 544 + c * 16,
                    g_vt + ((size_t)bh * 64 + r) * S_LEN + (nt + 1) * 128 + c * 4);
            }
            cp_commit();
        }

        const float* K   = (const float*)(sm + FL_K + (nt & 1) * 36864);
        const float* Vc  = (const float*)(sm + FL_V + (nt & 1) * 34816);
        const float* mbc = mb + (nt & 1) * 128;

        // acc init = mask bias + log2(1/l) per row  -> p = exp2(acc), bare
        float lr[2][2];
        #pragma unroll
        for (int mi = 0; mi < 2; mi++)
            #pragma unroll
            for (int hh = 0; hh < 2; hh++)
                lr[mi][hh] = il[wr * 32 + mi * 16 + g + hh * 8];

        float acc[2][4][4];
        #pragma unroll
        for (int nj = 0; nj < 4; nj++) {
            int cl = wc * 32 + nj * 8 + t4 * 2;
            float m0 = mbc[cl], m1 = mbc[cl + 1];
            #pragma unroll
            for (int mi = 0; mi < 2; mi++) {
                acc[mi][nj][0] = m0 + lr[mi][0];
                acc[mi][nj][1] = m1 + lr[mi][0];
                acc[mi][nj][2] = m0 + lr[mi][1];
                acc[mi][nj][3] = m1 + lr[mi][1];
            }
        }
        #pragma unroll
        for (int ks = 0; ks < 8; ks++) {
            float2 bb[4];
            #pragma unroll
            for (int nj = 0; nj < 4; nj++) {
                int rb = wc * 32 + nj * 8 + g;
                bb[nj] = *(const float2*)&K[rb * 72 + ks * 8 + t4 * 2];
            }
            #pragma unroll
            for (int mi = 0; mi < 2; mi++)
                #pragma unroll
                for (int nj = 0; nj < 4; nj++)
                    mma_tf32(acc[mi][nj], qf[ks][mi][0].x, qf[ks][mi][1].x,
                             qf[ks][mi][0].y, qf[ks][mi][1].y, bb[nj].x, bb[nj].y);
        }

        // ---- p = exp2(acc), write to probs + Ps ----
        #pragma unroll
        for (int mi = 0; mi < 2; mi++)
            #pragma unroll
            for (int hh = 0; hh < 2; hh++) {
                int r = wr * 32 + mi * 16 + g + hh * 8;
                #pragma unroll
                for (int nj = 0; nj < 4; nj++) {
                    int cl = wc * 32 + nj * 8 + t4 * 2;
                    float p0 = exp2f(acc[mi][nj][hh * 2]);
                    float p1 = exp2f(acc[mi][nj][hh * 2 + 1]);
                    float2 o; o.x = p0; o.y = p1;
                    *(float2*)(Pg + (size_t)r * S_LEN + nt * 128 + cl) = o;
                    int gb = r * 136 + (cl & ~7);
                    Ps[gb + pp0] = rna(p0);
                    Ps[gb + pp1] = rna(p1);
                }
            }

        __syncthreads();     // Ps visible; V(nt) already resident

        // ---- PV ----
        #pragma unroll
        for (int ks = 0; ks < 16; ks++) {
            float2 a0, a1, bb[4];
            int rb = wr2 * 16 + g;
            a0 = *(const float2*)&Ps[rb * 136 + ks * 8 + t4 * 2];
            a1 = *(const float2*)&Ps[(rb + 8) * 136 + ks * 8 + t4 * 2];
            #pragma unroll
            for (int nj = 0; nj < 4; nj++) {
                int vb = wc2 * 32 + nj * 8 + g;
                bb[nj] = *(const float2*)&Vc[vb * 136 + ks * 8 + t4 * 2];
            }
            #pragma unroll
            for (int nj = 0; nj < 4; nj++)
                mma_tf32(accPV[nj], a0.x, a1.x, a0.y, a1.y, bb[nj].x, bb[nj].y);
        }
        // no trailing sync: next tile's top sync protects buffer reuse
    }

    // ---- ctx write (perm8-interleaved) ----
    #pragma unroll
    for (int nj = 0; nj < 4; nj++) {
        int col = h * 64 + wc2 * 32 + nj * 8 + t4 * 2;
        int cb = col & ~7;
        #pragma unroll
        for (int hh = 0; hh < 2; hh++) {
            int row = b * S_LEN + q0 + wr2 * 16 + g + hh * 8;
            g_ctx[(size_t)row * D_DIM + cb + pp0] = rna(accPV[nj][hh * 2]);
            g_ctx[(size_t)row * D_DIM + cb + pp1] = rna(accPV[nj][hh * 2 + 1]);
        }
    }
}

// ---------------------------------------------------------------------------
extern "C" void kernel_launch(void* const* d_in, const int* in_sizes, int n_in,
                              void* d_out, int out_size)
{
    (void)in_sizes; (void)n_in; (void)out_size;

    const float* hidden = (const float*)d_in[0];
    const int*   mask   = (const int*)  d_in[1];
    const int*   stypes = (const int*)  d_in[2];
    const float* Wq = (const float*)d_in[3];
    const float* bq = (const float*)d_in[4];
    const float* Wk = (const float*)d_in[5];
    const float* bk = (const float*)d_in[6];
    const float* Wv = (const float*)d_in[7];
    const float* bv = (const float*)d_in[8];
    const float* Wo = (const float*)d_in[9];
    const float* bo = (const float*)d_in[10];
    const float* sw = (const float*)d_in[11];

    float* out   = (float*)d_out;
    float* probs = out + (size_t)M_ROWS * D_DIM;

    float *hidp, *wtp, *mbp;
    cudaGetSymbolAddress((void**)&hidp, g_hid);
    cudaGetSymbolAddress((void**)&wtp,  g_wt);
    cudaGetSymbolAddress((void**)&mbp,  g_mbias);

    cudaFuncSetAttribute(proj_qkv, cudaFuncAttributeMaxDynamicSharedMemorySize, PJ_SMEM);
    cudaFuncSetAttribute(proj_o,   cudaFuncAttributeMaxDynamicSharedMemorySize, PJ_SMEM);
    cudaFuncSetAttribute(flash_tf, cudaFuncAttributeMaxDynamicSharedMemorySize, FL_SMEM);

    // 524288 float4-pairs of hidden + 4096 mask-bias elements
    prep_hid<<<2064, 256>>>((const float4*)hidden, (float4*)hidp, 524288,
                            mask, mbp, 2 * S_LEN);
    prep_w<<<dim3(32, 32, 4), dim3(32, 8)>>>(Wq, Wk, Wv, Wo, wtp);

    proj_qkv<<<dim3(8, 32, 3), 256, PJ_SMEM>>>(bq, bk, bv, stypes, sw);

    flash_tf<<<dim3(16, 32), 512, FL_SMEM>>>(probs);

    proj_o<<<dim3(8, 32), 256, PJ_SMEM>>>(bo, out);
}

// round 12
// speedup vs baseline: 1.8002x; 1.6450x over previous
#include <cuda_runtime.h>
#include <cuda_fp16.h>
#include <math_constants.h>
#include <cstdint>

#define S_LEN  2048
#define D_DIM  1024
#define N_H    16
#define M_ROWS 4096

// ------------------------- device scratch (bss) ----------------------------
#define DEVBUF __device__ __align__(256)
DEVBUF __half g_hid[M_ROWS * D_DIM];       // fp16, natural [row][k]
DEVBUF __half g_wt [4 * D_DIM * D_DIM];    // W^T [n][k] fp16
DEVBUF __half g_q  [M_ROWS * D_DIM];       // [token][1024]
DEVBUF __half g_k  [M_ROWS * D_DIM];
DEVBUF __half g_vt [32 * 64 * S_LEN];      // [bh][d][token]
DEVBUF __half g_ctx[M_ROWS * D_DIM];
DEVBUF float  g_mbias[2 * S_LEN];          // mask ? 0 : -1e30

// ------------------------------ helpers ------------------------------------
__device__ __forceinline__ uint32_t smem_u32(const void* p) {
    return (uint32_t)__cvta_generic_to_shared(p);
}
__device__ __forceinline__ void ldm4(uint32_t* r, uint32_t a) {
    asm volatile("ldmatrix.sync.aligned.m8n8.x4.shared.b16 {%0,%1,%2,%3}, [%4];"
                 : "=r"(r[0]), "=r"(r[1]), "=r"(r[2]), "=r"(r[3]) : "r"(a));
}
__device__ __forceinline__ void mma_fp16(float* c, const uint32_t* a,
                                         uint32_t b0, uint32_t b1) {
    asm volatile("mma.sync.aligned.m16n8k16.row.col.f32.f16.f16.f32 "
                 "{%0,%1,%2,%3}, {%4,%5,%6,%7}, {%8,%9}, {%0,%1,%2,%3};"
                 : "+f"(c[0]), "+f"(c[1]), "+f"(c[2]), "+f"(c[3])
                 : "r"(a[0]), "r"(a[1]), "r"(a[2]), "r"(a[3]), "r"(b0), "r"(b1));
}
__device__ __forceinline__ void cpa(void* d, const void* s) {
    asm volatile("cp.async.cg.shared.global [%0], [%1], 16;"
                 :: "r"(smem_u32(d)), "l"(s));
}
__device__ __forceinline__ void cp_commit() { asm volatile("cp.async.commit_group;"); }
template<int N> __device__ __forceinline__ void cp_wait() {
    asm volatile("cp.async.wait_group %0;" :: "n"(N));
}

// ---------------------------------------------------------------------------
// prep: fp32 -> fp16 hidden (+ mask bias); transpose + fp16 weights
// ---------------------------------------------------------------------------
__global__ __launch_bounds__(256)
void prep_hid(const float4* __restrict__ in, uint4* __restrict__ out, int ng,
              const int* __restrict__ mask, float* __restrict__ mbias, int nb)
{
    int i = blockIdx.x * 256 + threadIdx.x;
    if (i < ng) {
        float4 v0 = in[i * 2], v1 = in[i * 2 + 1];
        __half2 h0 = __floats2half2_rn(v0.x, v0.y);
        __half2 h1 = __floats2half2_rn(v0.z, v0.w);
        __half2 h2 = __floats2half2_rn(v1.x, v1.y);
        __half2 h3 = __floats2half2_rn(v1.z, v1.w);
        uint4 o;
        o.x = *(uint32_t*)&h0; o.y = *(uint32_t*)&h1;
        o.z = *(uint32_t*)&h2; o.w = *(uint32_t*)&h3;
        out[i] = o;
    }
    int j = i - ng;
    if (j >= 0 && j < nb) mbias[j] = mask[j] ? 0.f : -1e30f;
}

__global__ __launch_bounds__(256)
void prep_w(const float* __restrict__ W0, const float* __restrict__ W1,
            const float* __restrict__ W2, const float* __restrict__ W3,
            __half* __restrict__ outbase)
{
    __shared__ float tile[32][33];
    const int z = blockIdx.z;
    const float* W = (z == 0) ? W0 : (z == 1) ? W1 : (z == 2) ? W2 : W3;
    __half* out = outbase + (size_t)z * D_DIM * D_DIM;
    const int tx = threadIdx.x, ty = threadIdx.y;
    const int x = blockIdx.x * 32 + tx, y0 = blockIdx.y * 32;
    #pragma unroll
    for (int i = 0; i < 4; i++)
        tile[ty + i * 8][tx] = W[(size_t)(y0 + ty + i * 8) * D_DIM + x];
    __syncthreads();
    #pragma unroll
    for (int i = 0; i < 4; i++) {
        int n = blockIdx.x * 32 + ty + i * 8;
        int k = y0 + tx;
        out[(size_t)n * D_DIM + k] = __float2half_rn(tile[tx][ty + i * 8]);
    }
}

// ---------------------------------------------------------------------------
// fp16 projection GEMM: 128x128 tile, BK=32, 8 warps (2x4), warp 64x32.
// Smem per stage: A[128][40]h + B[128][40]h (pitch 80B), ldmatrix frags.
// ---------------------------------------------------------------------------
#define PJ_B     10240
#define PJ_STG   20480
#define PJ_SMEM  (2 * PJ_STG)

__device__ __forceinline__ void proj_load(char* base, const __half* Ag,
                                          const __half* Bg, int bm, int bn,
                                          int k0, int t)
{
    #pragma unroll
    for (int j = 0; j < 2; j++) {
        int idx = j * 256 + t;
        int r = idx >> 2, c = idx & 3;
        cpa(base + r * 80 + c * 16,        Ag + (size_t)(bm + r) * D_DIM + k0 + c * 8);
        cpa(base + PJ_B + r * 80 + c * 16, Bg + (size_t)(bn + r) * D_DIM + k0 + c * 8);
    }
}

__device__ __forceinline__ void proj_mainloop(const __half* Ag, const __half* Bg,
                                              char* sm, int bm, int bn, int t,
                                              float acc[4][4][4])
{
    const int lane = t & 31, wid = t >> 5;
    const int wr = wid >> 2, wc = wid & 3;
    const int l15 = lane & 15, lhi = lane >> 4;
    const int brow = (lane & 7) + ((lane & 16) ? 8 : 0);
    const int bcol8 = (lane & 8) ? 8 : 0;

    proj_load(sm, Ag, Bg, bm, bn, 0, t);
    cp_commit();

    for (int c = 0; c < 32; c++) {
        if (c < 31) {
            proj_load(sm + ((c + 1) & 1) * PJ_STG, Ag, Bg, bm, bn, (c + 1) * 32, t);
            cp_commit();
            cp_wait<1>();
        } else {
            cp_wait<0>();
        }
        __syncthreads();
        const __half* A = (const __half*)(sm + (c & 1) * PJ_STG);
        const __half* B = (const __half*)(sm + (c & 1) * PJ_STG + PJ_B);
        #pragma unroll
        for (int kg = 0; kg < 2; kg++) {
            uint32_t af[4][4], bf[2][4];
            #pragma unroll
            for (int mi = 0; mi < 4; mi++)
                ldm4(af[mi], smem_u32(&A[(wr * 64 + mi * 16 + l15) * 40 + kg * 16 + lhi * 8]));
            #pragma unroll
            for (int ng = 0; ng < 2; ng++)
                ldm4(bf[ng], smem_u32(&B[(wc * 32 + ng * 16 + brow) * 40 + kg * 16 + bcol8]));
            #pragma unroll
            for (int mi = 0; mi < 4; mi++)
                #pragma unroll
                for (int nj = 0; nj < 4; nj++) {
                    int ng = nj >> 1, fo = (nj & 1) * 2;
                    mma_fp16(acc[mi][nj], af[mi], bf[ng][fo], bf[ng][fo + 1]);
                }
        }
        __syncthreads();
    }
}

__global__ __launch_bounds__(256, 2)
void proj_qkv(const float* __restrict__ bq, const float* __restrict__ bk,
              const float* __restrict__ bv, const int* __restrict__ stypes,
              const float* __restrict__ sw)
{
    extern __shared__ __align__(16) char sm[];
    const int t = threadIdx.x, lane = t & 31, wid = t >> 5;
    const int wr = wid >> 2, wc = wid & 3;
    const int g = lane >> 2, t4 = lane & 3;
    const int bm = blockIdx.y * 128, bn = blockIdx.x * 128;
    const int z = blockIdx.z;

    const float* bias = (z == 0) ? bq : (z == 1) ? bk : bv;
    const __half* Bg = g_wt + (size_t)z * D_DIM * D_DIM;

    float acc[4][4][4] = {};
    proj_mainloop(g_hid, Bg, sm, bm, bn, t, acc);

    const float QSCALE = 0.125f * 1.4426950408889634f;  // exp2 form
    #pragma unroll
    for (int mi = 0; mi < 4; mi++)
        #pragma unroll
        for (int nj = 0; nj < 4; nj++) {
            int col = bn + wc * 32 + nj * 8 + t4 * 2;
            float b0 = bias[col], b1 = bias[col + 1];
            #pragma unroll
            for (int hh = 0; hh < 2; hh++) {
                int row = bm + wr * 64 + mi * 16 + g + hh * 8;
                float s = 1.0f;
                if (z == 0) s = sw[stypes[row] * N_H + (col >> 6)] * QSCALE;
                float x = (acc[mi][nj][hh * 2]     + b0) * s;
                float y = (acc[mi][nj][hh * 2 + 1] + b1) * s;
                if (z < 2) {
                    __half* O = (z == 0) ? g_q : g_k;
                    *(__half2*)(O + (size_t)row * D_DIM + col) = __floats2half2_rn(x, y);
                } else {
                    int b = row >> 11, tok = row & 2047;
                    int hd = col >> 6, dl = col & 63;
                    size_t base = ((size_t)((b << 4) + hd) * 64 + dl) * S_LEN;
                    g_vt[base + tok]         = __float2half_rn(x);
                    g_vt[base + S_LEN + tok] = __float2half_rn(y);
                }
            }
        }
}

__global__ __launch_bounds__(256, 2)
void proj_o(const float* __restrict__ bias, float* __restrict__ Cf)
{
    extern __shared__ __align__(16) char sm[];
    const int t = threadIdx.x, lane = t & 31, wid = t >> 5;
    const int wr = wid >> 2, wc = wid & 3;
    const int g = lane >> 2, t4 = lane & 3;
    const int bm = blockIdx.y * 128, bn = blockIdx.x * 128;

    float acc[4][4][4] = {};
    proj_mainloop(g_ctx, g_wt + (size_t)3 * D_DIM * D_DIM, sm, bm, bn, t, acc);

    #pragma unroll
    for (int mi = 0; mi < 4; mi++)
        #pragma unroll
        for (int nj = 0; nj < 4; nj++) {
            int col = bn + wc * 32 + nj * 8 + t4 * 2;
            float b0 = bias[col], b1 = bias[col + 1];
            #pragma unroll
            for (int hh = 0; hh < 2; hh++) {
                int row = bm + wr * 64 + mi * 16 + g + hh * 8;
                float2 o;
                o.x = acc[mi][nj][hh * 2]     + b0;
                o.y = acc[mi][nj][hh * 2 + 1] + b1;
                *(float2*)(Cf + (size_t)row * D_DIM + col) = o;
            }
        }
}

// ---------------------------------------------------------------------------
// flash_fp16: fused two-pass flash attention (R11 structure, fp16 operands).
//  - mask bias + log2(1/l) folded into fp32 accumulator init
//  - Q A-frags cached in registers (ldmatrix once)
//  - pass 1: K triple-buffered (3rd buffer in V region), depth-2 prefetch
//  - pass 2: K+V double-buffered, full-tile prefetch
// 512 threads, 1 CTA/SM.
// ---------------------------------------------------------------------------
#define FL_K    0          // 2 x [128][72]h = 36864
#define FL_V    36864      // 2 x [64][136]h = 34816  (pass1: K buf2 here)
#define FL_PS   71680      // [128][136]h    = 34816  (stages Q [128][72]h)
#define FL_IL   106496     // float[128]
#define FL_MB   107008     // float[3][128]
#define FL_RED  108544     // float[4][128]
#define FL_SMEM 110592

__global__ __launch_bounds__(512, 1)
void flash_fp16(float* __restrict__ probs)
{
    extern __shared__ __align__(16) char sm[];
    const int t = threadIdx.x, lane = t & 31, wid = t >> 5;
    const int bh = blockIdx.y, b = bh >> 4, h = bh & 15;
    const int q0 = blockIdx.x * 128;
    const int g = lane >> 2, t4 = lane & 3;
    const int l15 = lane & 15, lhi = lane >> 4;
    const int brow = (lane & 7) + ((lane & 16) ? 8 : 0);
    const int bcol8 = (lane & 8) ? 8 : 0;

    __half* Ps  = (__half*)(sm + FL_PS);
    float* il   = (float*)(sm + FL_IL);
    float* mb   = (float*)(sm + FL_MB);
    float* red  = (float*)(sm + FL_RED);

    const int wr = wid >> 2, wc = wid & 3;     // QK: 32q x 32tok strips
    const int wr2 = wid >> 1, wc2 = wid & 1;   // PV: 16q x 32d strips

    const float* mbg = g_mbias + b * S_LEN;

    auto kb1 = [&](int i) -> char* {           // pass-1 triple K buffers
        return sm + (i == 2 ? FL_V : FL_K + i * 18432);
    };

    // preload group A: Q (staged in Ps, pitch 72h) + K(0) + mb(0)
    #pragma unroll
    for (int j = 0; j < 2; j++) {
        int idx = j * 512 + t;
        int r = idx >> 3, c = idx & 7;
        cpa((char*)Ps + r * 144 + c * 16,
            g_q + (size_t)(b * S_LEN + q0 + r) * D_DIM + h * 64 + c * 8);
    }
    #pragma unroll
    for (int j = 0; j < 2; j++) {
        int idx = j * 512 + t;
        int r = idx >> 3, c = idx & 7;
        cpa(kb1(0) + r * 144 + c * 16,
            g_k + (size_t)(b * S_LEN + r) * D_DIM + h * 64 + c * 8);
    }
    if (t < 32) cpa((char*)mb + t * 16, mbg + t * 4);
    cp_commit();
    // preload group B: K(1) + mb(1)
    #pragma unroll
    for (int j = 0; j < 2; j++) {
        int idx = j * 512 + t;
        int r = idx >> 3, c = idx & 7;
        cpa(kb1(1) + r * 144 + c * 16,
            g_k + (size_t)(b * S_LEN + 128 + r) * D_DIM + h * 64 + c * 8);
    }
    if (t < 32) cpa((char*)mb + 512 + t * 16, mbg + 128 + t * 4);
    cp_commit();

    cp_wait<1>();
    __syncthreads();

    // Q A-fragments -> registers (ldmatrix once; shared across both passes)
    uint32_t qf[4][2][4];
    {
        const __half* Qs = (const __half*)Ps;
        #pragma unroll
        for (int kg = 0; kg < 4; kg++)
            #pragma unroll
            for (int mi = 0; mi < 2; mi++)
                ldm4(qf[kg][mi],
                     smem_u32(&Qs[(wr * 32 + mi * 16 + l15) * 72 + kg * 16 + lhi * 8]));
    }

    float lp[2][2] = {};

    // =================== pass 1: row sums ===================
    for (int nt = 0; nt < 16; nt++) {
        if (nt > 0) {
            if (nt < 15) cp_wait<1>(); else cp_wait<0>();
            __syncthreads();
        }
        if (nt + 2 <= 15) {
            int dst = (nt + 2) % 3;
            #pragma unroll
            for (int j = 0; j < 2; j++) {
                int idx = j * 512 + t;
                int r = idx >> 3, c = idx & 7;
                cpa(kb1(dst) + r * 144 + c * 16,
                    g_k + (size_t)(b * S_LEN + (nt + 2) * 128 + r) * D_DIM + h * 64 + c * 8);
            }
            if (t < 32) cpa((char*)mb + dst * 512 + t * 16, mbg + (nt + 2) * 128 + t * 4);
            cp_commit();
        }

        const __half* K = (const __half*)kb1(nt % 3);
        const float* mbc = mb + (nt % 3) * 128;

        float acc[2][4][4];
        #pragma unroll
        for (int nj = 0; nj < 4; nj++) {
            int cl = wc * 32 + nj * 8 + t4 * 2;
            float m0 = mbc[cl], m1 = mbc[cl + 1];
            #pragma unroll
            for (int mi = 0; mi < 2; mi++) {
                acc[mi][nj][0] = m0; acc[mi][nj][1] = m1;
                acc[mi][nj][2] = m0; acc[mi][nj][3] = m1;
            }
        }
        #pragma unroll
        for (int kg = 0; kg < 4; kg++) {
            uint32_t bf[2][4];
            #pragma unroll
            for (int ng = 0; ng < 2; ng++)
                ldm4(bf[ng], smem_u32(&K[(wc * 32 + ng * 16 + brow) * 72 + kg * 16 + bcol8]));
            #pragma unroll
            for (int mi = 0; mi < 2; mi++)
                #pragma unroll
                for (int nj = 0; nj < 4; nj++) {
                    int ng = nj >> 1, fo = (nj & 1) * 2;
                    mma_fp16(acc[mi][nj], qf[kg][mi], bf[ng][fo], bf[ng][fo + 1]);
                }
        }

        #pragma unroll
        for (int mi = 0; mi < 2; mi++)
            #pragma unroll
            for (int hh = 0; hh < 2; hh++) {
                float s = 0.f;
                #pragma unroll
                for (int nj = 0; nj < 4; nj++)
                    s += exp2f(acc[mi][nj][hh * 2]) + exp2f(acc[mi][nj][hh * 2 + 1]);
                s += __shfl_xor_sync(0xffffffffu, s, 1);
                s += __shfl_xor_sync(0xffffffffu, s, 2);
                lp[mi][hh] += s;
            }
    }

    if (t4 == 0)
        #pragma unroll
        for (int mi = 0; mi < 2; mi++)
            #pragma unroll
            for (int hh = 0; hh < 2; hh++)
                red[wc * 128 + wr * 32 + mi * 16 + g + hh * 8] = lp[mi][hh];
    __syncthreads();
    if (t < 128)
        il[t] = -__log2f(red[t] + red[128 + t] + red[256 + t] + red[384 + t]);

    // preload pass 2: ONE group = K(0) + mb(0) + V(0)
    #pragma unroll
    for (int j = 0; j < 2; j++) {
        int idx = j * 512 + t;
        int r = idx >> 3, c = idx & 7;
        cpa(sm + FL_K + r * 144 + c * 16,
            g_k + (size_t)(b * S_LEN + r) * D_DIM + h * 64 + c * 8);
    }
    if (t < 32) cpa((char*)mb + t * 16, mbg + t * 4);
    #pragma unroll
    for (int j = 0; j < 2; j++) {
        int idx = j * 512 + t;
        int r = idx >> 4, c = idx & 15;
        cpa(sm + FL_V + r * 272 + c * 16,
            g_vt + ((size_t)bh * 64 + r) * S_LEN + c * 8);
    }
    cp_commit();

    // =================== pass 2: emit probs + PV ===================
    float accPV[4][4] = {};
    float* Pg = probs + ((size_t)bh * S_LEN + q0) * S_LEN;

    for (int nt = 0; nt < 16; nt++) {
        cp_wait<0>();
        __syncthreads();

        if (nt < 15) {
            #pragma unroll
            for (int j = 0; j < 2; j++) {
                int idx = j * 512 + t;
                int r = idx >> 3, c = idx & 7;
                cpa(sm + FL_K + ((nt + 1) & 1) * 18432 + r * 144 + c * 16,
                    g_k + (size_t)(b * S_LEN + (nt + 1) * 128 + r) * D_DIM + h * 64 + c * 8);
            }
            if (t < 32) cpa((char*)mb + ((nt + 1) & 1) * 512 + t * 16,
                            mbg + (nt + 1) * 128 + t * 4);
            #pragma unroll
            for (int j = 0; j < 2; j++) {
                int idx = j * 512 + t;
                int r = idx >> 4, c = idx & 15;
                cpa(sm + FL_V + ((nt + 1) & 1) * 17408 + r * 272 + c * 16,
                    g_vt + ((size_t)bh * 64 + r) * S_LEN + (nt + 1) * 128 + c * 8);
            }
            cp_commit();
        }

        const __half* K   = (const __half*)(sm + FL_K + (nt & 1) * 18432);
        const __half* Vc  = (const __half*)(sm + FL_V + (nt & 1) * 17408);
        const float* mbc  = mb + (nt & 1) * 128;

        float lr[2][2];
        #pragma unroll
        for (int mi = 0; mi < 2; mi++)
            #pragma unroll
            for (int hh = 0; hh < 2; hh++)
                lr[mi][hh] = il[wr * 32 + mi * 16 + g + hh * 8];

        float acc[2][4][4];
        #pragma unroll
        for (int nj = 0; nj < 4; nj++) {
            int cl = wc * 32 + nj * 8 + t4 * 2;
            float m0 = mbc[cl], m1 = mbc[cl + 1];
            #pragma unroll
            for (int mi = 0; mi < 2; mi++) {
                acc[mi][nj][0] = m0 + lr[mi][0];
                acc[mi][nj][1] = m1 + lr[mi][0];
                acc[mi][nj][2] = m0 + lr[mi][1];
                acc[mi][nj][3] = m1 + lr[mi][1];
            }
        }
        #pragma unroll
        for (int kg = 0; kg < 4; kg++) {
            uint32_t bf[2][4];
            #pragma unroll
            for (int ng = 0; ng < 2; ng++)
                ldm4(bf[ng], smem_u32(&K[(wc * 32 + ng * 16 + brow) * 72 + kg * 16 + bcol8]));
            #pragma unroll
            for (int mi = 0; mi < 2; mi++)
                #pragma unroll
                for (int nj = 0; nj < 4; nj++) {
                    int ng = nj >> 1, fo = (nj & 1) * 2;
                    mma_fp16(acc[mi][nj], qf[kg][mi], bf[ng][fo], bf[ng][fo + 1]);
                }
        }

        // p = exp2(acc): write fp32 to probs, fp16 to Ps
        #pragma unroll
        for (int mi = 0; mi < 2; mi++)
            #pragma unroll
            for (int hh = 0; hh < 2; hh++) {
                int r = wr * 32 + mi * 16 + g + hh * 8;
                #pragma unroll
                for (int nj = 0; nj < 4; nj++) {
                    int cl = wc * 32 + nj * 8 + t4 * 2;
                    float p0 = exp2f(acc[mi][nj][hh * 2]);
                    float p1 = exp2f(acc[mi][nj][hh * 2 + 1]);
                    float2 o; o.x = p0; o.y = p1;
                    *(float2*)(Pg + (size_t)r * S_LEN + nt * 128 + cl) = o;
                    *(__half2*)(Ps + r * 136 + cl) = __floats2half2_rn(p0, p1);
                }
            }

        __syncthreads();     // Ps visible; V(nt) resident

        // ---- PV (ldmatrix frags) ----
        #pragma unroll
        for (int kg = 0; kg < 8; kg++) {
            uint32_t af[4], bf[2][4];
            ldm4(af, smem_u32(&Ps[(wr2 * 16 + l15) * 136 + kg * 16 + lhi * 8]));
            #pragma unroll
            for (int ng = 0; ng < 2; ng++)
                ldm4(bf[ng], smem_u32(&Vc[(wc2 * 32 + ng * 16 + brow) * 136 + kg * 16 + bcol8]));
            #pragma unroll
            for (int nj = 0; nj < 4; nj++) {
                int ng = nj >> 1, fo = (nj & 1) * 2;
                mma_fp16(accPV[nj], af, bf[ng][fo], bf[ng][fo + 1]);
            }
        }
        // no trailing sync: next tile's top sync protects buffer reuse
    }

    // ---- ctx write (fp16) ----
    #pragma unroll
    for (int nj = 0; nj < 4; nj++) {
        int col = h * 64 + wc2 * 32 + nj * 8 + t4 * 2;
        #pragma unroll
        for (int hh = 0; hh < 2; hh++) {
            int row = b * S_LEN + q0 + wr2 * 16 + g + hh * 8;
            *(__half2*)(g_ctx + (size_t)row * D_DIM + col) =
                __floats2half2_rn(accPV[nj][hh * 2], accPV[nj][hh * 2 + 1]);
        }
    }
}

// ---------------------------------------------------------------------------
extern "C" void kernel_launch(void* const* d_in, const int* in_sizes, int n_in,
                              void* d_out, int out_size)
{
    (void)in_sizes; (void)n_in; (void)out_size;

    const float* hidden = (const float*)d_in[0];
    const int*   mask   = (const int*)  d_in[1];
    const int*   stypes = (const int*)  d_in[2];
    const float* Wq = (const float*)d_in[3];
    const float* bq = (const float*)d_in[4];
    const float* Wk = (const float*)d_in[5];
    const float* bk = (const float*)d_in[6];
    const float* Wv = (const float*)d_in[7];
    const float* bv = (const float*)d_in[8];
    const float* Wo = (const float*)d_in[9];
    const float* bo = (const float*)d_in[10];
    const float* sw = (const float*)d_in[11];

    float* out   = (float*)d_out;
    float* probs = out + (size_t)M_ROWS * D_DIM;

    __half *hidp, *wtp;
    float *mbp;
    cudaGetSymbolAddress((void**)&hidp, g_hid);
    cudaGetSymbolAddress((void**)&wtp,  g_wt);
    cudaGetSymbolAddress((void**)&mbp,  g_mbias);

    cudaFuncSetAttribute(proj_qkv,   cudaFuncAttributeMaxDynamicSharedMemorySize, PJ_SMEM);
    cudaFuncSetAttribute(proj_o,     cudaFuncAttributeMaxDynamicSharedMemorySize, PJ_SMEM);
    cudaFuncSetAttribute(flash_fp16, cudaFuncAttributeMaxDynamicSharedMemorySize, FL_SMEM);

    prep_hid<<<2064, 256>>>((const float4*)hidden, (uint4*)hidp, 524288,
                            mask, mbp, 2 * S_LEN);
    prep_w<<<dim3(32, 32, 4), dim3(32, 8)>>>(Wq, Wk, Wv, Wo, wtp);

    proj_qkv<<<dim3(8, 32, 3), 256, PJ_SMEM>>>(bq, bk, bv, stypes, sw);

    flash_fp16<<<dim3(16, 32), 512, FL_SMEM>>>(probs);

    proj_o<<<dim3(8, 32), 256, PJ_SMEM>>>(bo, out);
}

// round 13
// speedup vs baseline: 1.9756x; 1.0975x over previous
#include <cuda_runtime.h>
#include <cuda_fp16.h>
#include <math_constants.h>
#include <cstdint>

#define S_LEN  2048
#define D_DIM  1024
#define N_H    16
#define M_ROWS 4096

// ------------------------- device scratch (bss) ----------------------------
#define DEVBUF __device__ __align__(256)
DEVBUF __half g_hid[M_ROWS * D_DIM];       // fp16, natural [row][k]
DEVBUF __half g_wt [4 * D_DIM * D_DIM];    // W^T [n][k] fp16
DEVBUF __half g_q  [M_ROWS * D_DIM];       // [token][1024]
DEVBUF __half g_k  [M_ROWS * D_DIM];
DEVBUF __half g_vt [32 * 64 * S_LEN];      // [bh][d][token]
DEVBUF __half g_ctx[M_ROWS * D_DIM];
DEVBUF float  g_mbias[2 * S_LEN];          // mask ? 0 : -1e30

// ------------------------------ helpers ------------------------------------
__device__ __forceinline__ uint32_t smem_u32(const void* p) {
    return (uint32_t)__cvta_generic_to_shared(p);
}
__device__ __forceinline__ void ldm4(uint32_t* r, uint32_t a) {
    asm volatile("ldmatrix.sync.aligned.m8n8.x4.shared.b16 {%0,%1,%2,%3}, [%4];"
                 : "=r"(r[0]), "=r"(r[1]), "=r"(r[2]), "=r"(r[3]) : "r"(a));
}
__device__ __forceinline__ void mma_fp16(float* c, const uint32_t* a,
                                         uint32_t b0, uint32_t b1) {
    asm volatile("mma.sync.aligned.m16n8k16.row.col.f32.f16.f16.f32 "
                 "{%0,%1,%2,%3}, {%4,%5,%6,%7}, {%8,%9}, {%0,%1,%2,%3};"
                 : "+f"(c[0]), "+f"(c[1]), "+f"(c[2]), "+f"(c[3])
                 : "r"(a[0]), "r"(a[1]), "r"(a[2]), "r"(a[3]), "r"(b0), "r"(b1));
}
__device__ __forceinline__ void cpa(void* d, const void* s) {
    asm volatile("cp.async.cg.shared.global [%0], [%1], 16;"
                 :: "r"(smem_u32(d)), "l"(s));
}
__device__ __forceinline__ void cp_commit() { asm volatile("cp.async.commit_group;"); }
template<int N> __device__ __forceinline__ void cp_wait() {
    asm volatile("cp.async.wait_group %0;" :: "n"(N));
}

// ---------------------------------------------------------------------------
// prep: fp32 -> fp16 hidden (+ mask bias); transpose + fp16 weights
// ---------------------------------------------------------------------------
__global__ __launch_bounds__(256)
void prep_hid(const float4* __restrict__ in, uint4* __restrict__ out, int ng,
              const int* __restrict__ mask, float* __restrict__ mbias, int nb)
{
    int i = blockIdx.x * 256 + threadIdx.x;
    if (i < ng) {
        float4 v0 = in[i * 2], v1 = in[i * 2 + 1];
        __half2 h0 = __floats2half2_rn(v0.x, v0.y);
        __half2 h1 = __floats2half2_rn(v0.z, v0.w);
        __half2 h2 = __floats2half2_rn(v1.x, v1.y);
        __half2 h3 = __floats2half2_rn(v1.z, v1.w);
        uint4 o;
        o.x = *(uint32_t*)&h0; o.y = *(uint32_t*)&h1;
        o.z = *(uint32_t*)&h2; o.w = *(uint32_t*)&h3;
        out[i] = o;
    }
    int j = i - ng;
    if (j >= 0 && j < nb) mbias[j] = mask[j] ? 0.f : -1e30f;
}

__global__ __launch_bounds__(256)
void prep_w(const float* __restrict__ W0, const float* __restrict__ W1,
            const float* __restrict__ W2, const float* __restrict__ W3,
            __half* __restrict__ outbase)
{
    __shared__ float tile[32][33];
    const int z = blockIdx.z;
    const float* W = (z == 0) ? W0 : (z == 1) ? W1 : (z == 2) ? W2 : W3;
    __half* out = outbase + (size_t)z * D_DIM * D_DIM;
    const int tx = threadIdx.x, ty = threadIdx.y;
    const int x = blockIdx.x * 32 + tx, y0 = blockIdx.y * 32;
    #pragma unroll
    for (int i = 0; i < 4; i++)
        tile[ty + i * 8][tx] = W[(size_t)(y0 + ty + i * 8) * D_DIM + x];
    __syncthreads();
    #pragma unroll
    for (int i = 0; i < 4; i++) {
        int n = blockIdx.x * 32 + ty + i * 8;
        int k = y0 + tx;
        out[(size_t)n * D_DIM + k] = __float2half_rn(tile[tx][ty + i * 8]);
    }
}

// ---------------------------------------------------------------------------
// fp16 projection GEMM (unchanged from R12)
// ---------------------------------------------------------------------------
#define PJ_B     10240
#define PJ_STG   20480
#define PJ_SMEM  (2 * PJ_STG)

__device__ __forceinline__ void proj_load(char* base, const __half* Ag,
                                          const __half* Bg, int bm, int bn,
                                          int k0, int t)
{
    #pragma unroll
    for (int j = 0; j < 2; j++) {
        int idx = j * 256 + t;
        int r = idx >> 2, c = idx & 3;
        cpa(base + r * 80 + c * 16,        Ag + (size_t)(bm + r) * D_DIM + k0 + c * 8);
        cpa(base + PJ_B + r * 80 + c * 16, Bg + (size_t)(bn + r) * D_DIM + k0 + c * 8);
    }
}

__device__ __forceinline__ void proj_mainloop(const __half* Ag, const __half* Bg,
                                              char* sm, int bm, int bn, int t,
                                              float acc[4][4][4])
{
    const int lane = t & 31, wid = t >> 5;
    const int wr = wid >> 2, wc = wid & 3;
    const int l15 = lane & 15, lhi = lane >> 4;
    const int brow = (lane & 7) + ((lane & 16) ? 8 : 0);
    const int bcol8 = (lane & 8) ? 8 : 0;

    proj_load(sm, Ag, Bg, bm, bn, 0, t);
    cp_commit();

    for (int c = 0; c < 32; c++) {
        if (c < 31) {
            proj_load(sm + ((c + 1) & 1) * PJ_STG, Ag, Bg, bm, bn, (c + 1) * 32, t);
            cp_commit();
            cp_wait<1>();
        } else {
            cp_wait<0>();
        }
        __syncthreads();
        const __half* A = (const __half*)(sm + (c & 1) * PJ_STG);
        const __half* B = (const __half*)(sm + (c & 1) * PJ_STG + PJ_B);
        #pragma unroll
        for (int kg = 0; kg < 2; kg++) {
            uint32_t af[4][4], bf[2][4];
            #pragma unroll
            for (int mi = 0; mi < 4; mi++)
                ldm4(af[mi], smem_u32(&A[(wr * 64 + mi * 16 + l15) * 40 + kg * 16 + lhi * 8]));
            #pragma unroll
            for (int ng = 0; ng < 2; ng++)
                ldm4(bf[ng], smem_u32(&B[(wc * 32 + ng * 16 + brow) * 40 + kg * 16 + bcol8]));
            #pragma unroll
            for (int mi = 0; mi < 4; mi++)
                #pragma unroll
                for (int nj = 0; nj < 4; nj++) {
                    int ng = nj >> 1, fo = (nj & 1) * 2;
                    mma_fp16(acc[mi][nj], af[mi], bf[ng][fo], bf[ng][fo + 1]);
                }
        }
        __syncthreads();
    }
}

__global__ __launch_bounds__(256, 2)
void proj_qkv(const float* __restrict__ bq, const float* __restrict__ bk,
              const float* __restrict__ bv, const int* __restrict__ stypes,
              const float* __restrict__ sw)
{
    extern __shared__ __align__(16) char sm[];
    const int t = threadIdx.x, lane = t & 31, wid = t >> 5;
    const int wr = wid >> 2, wc = wid & 3;
    const int g = lane >> 2, t4 = lane & 3;
    const int bm = blockIdx.y * 128, bn = blockIdx.x * 128;
    const int z = blockIdx.z;

    const float* bias = (z == 0) ? bq : (z == 1) ? bk : bv;
    const __half* Bg = g_wt + (size_t)z * D_DIM * D_DIM;

    float acc[4][4][4] = {};
    proj_mainloop(g_hid, Bg, sm, bm, bn, t, acc);

    const float QSCALE = 0.125f * 1.4426950408889634f;  // exp2 form
    #pragma unroll
    for (int mi = 0; mi < 4; mi++)
        #pragma unroll
        for (int nj = 0; nj < 4; nj++) {
            int col = bn + wc * 32 + nj * 8 + t4 * 2;
            float b0 = bias[col], b1 = bias[col + 1];
            #pragma unroll
            for (int hh = 0; hh < 2; hh++) {
                int row = bm + wr * 64 + mi * 16 + g + hh * 8;
                float s = 1.0f;
                if (z == 0) s = sw[stypes[row] * N_H + (col >> 6)] * QSCALE;
                float x = (acc[mi][nj][hh * 2]     + b0) * s;
                float y = (acc[mi][nj][hh * 2 + 1] + b1) * s;
                if (z < 2) {
                    __half* O = (z == 0) ? g_q : g_k;
                    *(__half2*)(O + (size_t)row * D_DIM + col) = __floats2half2_rn(x, y);
                } else {
                    int b = row >> 11, tok = row & 2047;
                    int hd = col >> 6, dl = col & 63;
                    size_t base = ((size_t)((b << 4) + hd) * 64 + dl) * S_LEN;
                    g_vt[base + tok]         = __float2half_rn(x);
                    g_vt[base + S_LEN + tok] = __float2half_rn(y);
                }
            }
        }
}

__global__ __launch_bounds__(256, 2)
void proj_o(const float* __restrict__ bias, float* __restrict__ Cf)
{
    extern __shared__ __align__(16) char sm[];
    const int t = threadIdx.x, lane = t & 31, wid = t >> 5;
    const int wr = wid >> 2, wc = wid & 3;
    const int g = lane >> 2, t4 = lane & 3;
    const int bm = blockIdx.y * 128, bn = blockIdx.x * 128;

    float acc[4][4][4] = {};
    proj_mainloop(g_ctx, g_wt + (size_t)3 * D_DIM * D_DIM, sm, bm, bn, t, acc);

    #pragma unroll
    for (int mi = 0; mi < 4; mi++)
        #pragma unroll
        for (int nj = 0; nj < 4; nj++) {
            int col = bn + wc * 32 + nj * 8 + t4 * 2;
            float b0 = bias[col], b1 = bias[col + 1];
            #pragma unroll
            for (int hh = 0; hh < 2; hh++) {
                int row = bm + wr * 64 + mi * 16 + g + hh * 8;
                float2 o;
                o.x = acc[mi][nj][hh * 2]     + b0;
                o.y = acc[mi][nj][hh * 2 + 1] + b1;
                *(float2*)(Cf + (size_t)row * D_DIM + col) = o;
            }
        }
}

// ---------------------------------------------------------------------------
// flash_fp16: BM=64 q rows, 256 threads, 2 CTAs/SM.
// Same warp tiles as R12 (QK 32qx32tok, PV 16qx32d); same pipeline structure.
//  - mask bias + log2(1/l) folded into fp32 accumulator init
//  - Q A-frags cached in registers
//  - pass 1: K triple-buffered (3rd buffer in V region), depth-2 prefetch
//  - pass 2: K+V double-buffered, full-tile prefetch
// ---------------------------------------------------------------------------
#define FL_K    0          // 2 x [128][72]h = 36864
#define FL_V    36864      // 2 x [64][136]h = 34816  (pass1: K buf2 here)
#define FL_PS   71680      // [64][136]h     = 17408  (stages Q [64][72]h)
#define FL_IL   89088      // float[64]
#define FL_MB   89344      // float[3][128]
#define FL_RED  90880      // float[4][64]
#define FL_SMEM 92160

__global__ __launch_bounds__(256, 2)
void flash_fp16(float* __restrict__ probs)
{
    extern __shared__ __align__(16) char sm[];
    const int t = threadIdx.x, lane = t & 31, wid = t >> 5;
    const int bh = blockIdx.y, b = bh >> 4, h = bh & 15;
    const int q0 = blockIdx.x * 64;
    const int g = lane >> 2, t4 = lane & 3;
    const int l15 = lane & 15, lhi = lane >> 4;
    const int brow = (lane & 7) + ((lane & 16) ? 8 : 0);
    const int bcol8 = (lane & 8) ? 8 : 0;

    __half* Ps  = (__half*)(sm + FL_PS);
    float* il   = (float*)(sm + FL_IL);
    float* mb   = (float*)(sm + FL_MB);
    float* red  = (float*)(sm + FL_RED);

    const int wr = wid >> 2, wc = wid & 3;     // QK: 32q x 32tok strips (wr 0..1)
    const int wr2 = wid >> 1, wc2 = wid & 1;   // PV: 16q x 32d strips  (wr2 0..3)

    const float* mbg = g_mbias + b * S_LEN;

    auto kb1 = [&](int i) -> char* {           // pass-1 triple K buffers
        return sm + (i == 2 ? FL_V : FL_K + i * 18432);
    };

    // preload group A: Q (staged in Ps, pitch 72h, 64 rows) + K(0) + mb(0)
    #pragma unroll
    for (int j = 0; j < 2; j++) {
        int idx = j * 256 + t;
        int r = idx >> 3, c = idx & 7;
        cpa((char*)Ps + r * 144 + c * 16,
            g_q + (size_t)(b * S_LEN + q0 + r) * D_DIM + h * 64 + c * 8);
    }
    #pragma unroll
    for (int j = 0; j < 4; j++) {
        int idx = j * 256 + t;
        int r = idx >> 3, c = idx & 7;
        cpa(kb1(0) + r * 144 + c * 16,
            g_k + (size_t)(b * S_LEN + r) * D_DIM + h * 64 + c * 8);
    }
    if (t < 32) cpa((char*)mb + t * 16, mbg + t * 4);
    cp_commit();
    // preload group B: K(1) + mb(1)
    #pragma unroll
    for (int j = 0; j < 4; j++) {
        int idx = j * 256 + t;
        int r = idx >> 3, c = idx & 7;
        cpa(kb1(1) + r * 144 + c * 16,
            g_k + (size_t)(b * S_LEN + 128 + r) * D_DIM + h * 64 + c * 8);
    }
    if (t < 32) cpa((char*)mb + 512 + t * 16, mbg + 128 + t * 4);
    cp_commit();

    cp_wait<1>();
    __syncthreads();

    // Q A-fragments -> registers (rows wr*32 + mi*16, wr in 0..1 -> 0..63)
    uint32_t qf[4][2][4];
    {
        const __half* Qs = (const __half*)Ps;
        #pragma unroll
        for (int kg = 0; kg < 4; kg++)
            #pragma unroll
            for (int mi = 0; mi < 2; mi++)
                ldm4(qf[kg][mi],
                     smem_u32(&Qs[(wr * 32 + mi * 16 + l15) * 72 + kg * 16 + lhi * 8]));
    }

    float lp[2][2] = {};

    // =================== pass 1: row sums ===================
    for (int nt = 0; nt < 16; nt++) {
        if (nt > 0) {
            if (nt < 15) cp_wait<1>(); else cp_wait<0>();
            __syncthreads();
        }
        if (nt + 2 <= 15) {
            int dst = (nt + 2) % 3;
            #pragma unroll
            for (int j = 0; j < 4; j++) {
                int idx = j * 256 + t;
                int r = idx >> 3, c = idx & 7;
                cpa(kb1(dst) + r * 144 + c * 16,
                    g_k + (size_t)(b * S_LEN + (nt + 2) * 128 + r) * D_DIM + h * 64 + c * 8);
            }
            if (t < 32) cpa((char*)mb + dst * 512 + t * 16, mbg + (nt + 2) * 128 + t * 4);
            cp_commit();
        }

        const __half* K = (const __half*)kb1(nt % 3);
        const float* mbc = mb + (nt % 3) * 128;

        float acc[2][4][4];
        #pragma unroll
        for (int nj = 0; nj < 4; nj++) {
            int cl = wc * 32 + nj * 8 + t4 * 2;
            float m0 = mbc[cl], m1 = mbc[cl + 1];
            #pragma unroll
            for (int mi = 0; mi < 2; mi++) {
                acc[mi][nj][0] = m0; acc[mi][nj][1] = m1;
                acc[mi][nj][2] = m0; acc[mi][nj][3] = m1;
            }
        }
        #pragma unroll
        for (int kg = 0; kg < 4; kg++) {
            uint32_t bf[2][4];
            #pragma unroll
            for (int ng = 0; ng < 2; ng++)
                ldm4(bf[ng], smem_u32(&K[(wc * 32 + ng * 16 + brow) * 72 + kg * 16 + bcol8]));
            #pragma unroll
            for (int mi = 0; mi < 2; mi++)
                #pragma unroll
                for (int nj = 0; nj < 4; nj++) {
                    int ng = nj >> 1, fo = (nj & 1) * 2;
                    mma_fp16(acc[mi][nj], qf[kg][mi], bf[ng][fo], bf[ng][fo + 1]);
                }
        }

        #pragma unroll
        for (int mi = 0; mi < 2; mi++)
            #pragma unroll
            for (int hh = 0; hh < 2; hh++) {
                float s = 0.f;
                #pragma unroll
                for (int nj = 0; nj < 4; nj++)
                    s += exp2f(acc[mi][nj][hh * 2]) + exp2f(acc[mi][nj][hh * 2 + 1]);
                s += __shfl_xor_sync(0xffffffffu, s, 1);
                s += __shfl_xor_sync(0xffffffffu, s, 2);
                lp[mi][hh] += s;
            }
    }

    if (t4 == 0)
        #pragma unroll
        for (int mi = 0; mi < 2; mi++)
            #pragma unroll
            for (int hh = 0; hh < 2; hh++)
                red[wc * 64 + wr * 32 + mi * 16 + g + hh * 8] = lp[mi][hh];
    __syncthreads();
    if (t < 64)
        il[t] = -__log2f(red[t] + red[64 + t] + red[128 + t] + red[192 + t]);

    // preload pass 2: ONE group = K(0) + mb(0) + V(0)
    #pragma unroll
    for (int j = 0; j < 4; j++) {
        int idx = j * 256 + t;
        int r = idx >> 3, c = idx & 7;
        cpa(sm + FL_K + r * 144 + c * 16,
            g_k + (size_t)(b * S_LEN + r) * D_DIM + h * 64 + c * 8);
    }
    if (t < 32) cpa((char*)mb + t * 16, mbg + t * 4);
    #pragma unroll
    for (int j = 0; j < 4; j++) {
        int idx = j * 256 + t;
        int r = idx >> 4, c = idx & 15;
        cpa(sm + FL_V + r * 272 + c * 16,
            g_vt + ((size_t)bh * 64 + r) * S_LEN + c * 8);
    }
    cp_commit();

    // =================== pass 2: emit probs + PV ===================
    float accPV[4][4] = {};
    float* Pg = probs + ((size_t)bh * S_LEN + q0) * S_LEN;

    for (int nt = 0; nt < 16; nt++) {
        cp_wait<0>();
        __syncthreads();

        if (nt < 15) {
            #pragma unroll
            for (int j = 0; j < 4; j++) {
                int idx = j * 256 + t;
                int r = idx >> 3, c = idx & 7;
                cpa(sm + FL_K + ((nt + 1) & 1) * 18432 + r * 144 + c * 16,
                    g_k + (size_t)(b * S_LEN + (nt + 1) * 128 + r) * D_DIM + h * 64 + c * 8);
            }
            if (t < 32) cpa((char*)mb + ((nt + 1) & 1) * 512 + t * 16,
                            mbg + (nt + 1) * 128 + t * 4);
            #pragma unroll
            for (int j = 0; j < 4; j++) {
                int idx = j * 256 + t;
                int r = idx >> 4, c = idx & 15;
                cpa(sm + FL_V + ((nt + 1) & 1) * 17408 + r * 272 + c * 16,
                    g_vt + ((size_t)bh * 64 + r) * S_LEN + (nt + 1) * 128 + c * 8);
            }
            cp_commit();
        }

        const __half* K   = (const __half*)(sm + FL_K + (nt & 1) * 18432);
        const __half* Vc  = (const __half*)(sm + FL_V + (nt & 1) * 17408);
        const float* mbc  = mb + (nt & 1) * 128;

        float lr[2][2];
        #pragma unroll
        for (int mi = 0; mi < 2; mi++)
            #pragma unroll
            for (int hh = 0; hh < 2; hh++)
                lr[mi][hh] = il[wr * 32 + mi * 16 + g + hh * 8];

        float acc[2][4][4];
        #pragma unroll
        for (int nj = 0; nj < 4; nj++) {
            int cl = wc * 32 + nj * 8 + t4 * 2;
            float m0 = mbc[cl], m1 = mbc[cl + 1];
            #pragma unroll
            for (int mi = 0; mi < 2; mi++) {
                acc[mi][nj][0] = m0 + lr[mi][0];
                acc[mi][nj][1] = m1 + lr[mi][0];
                acc[mi][nj][2] = m0 + lr[mi][1];
                acc[mi][nj][3] = m1 + lr[mi][1];
            }
        }
        #pragma unroll
        for (int kg = 0; kg < 4; kg++) {
            uint32_t bf[2][4];
            #pragma unroll
            for (int ng = 0; ng < 2; ng++)
                ldm4(bf[ng], smem_u32(&K[(wc * 32 + ng * 16 + brow) * 72 + kg * 16 + bcol8]));
            #pragma unroll
            for (int mi = 0; mi < 2; mi++)
                #pragma unroll
                for (int nj = 0; nj < 4; nj++) {
                    int ng = nj >> 1, fo = (nj & 1) * 2;
                    mma_fp16(acc[mi][nj], qf[kg][mi], bf[ng][fo], bf[ng][fo + 1]);
                }
        }

        // p = exp2(acc): write fp32 to probs, fp16 to Ps
        #pragma unroll
        for (int mi = 0; mi < 2; mi++)
            #pragma unroll
            for (int hh = 0; hh < 2; hh++) {
                int r = wr * 32 + mi * 16 + g + hh * 8;
                #pragma unroll
                for (int nj = 0; nj < 4; nj++) {
                    int cl = wc * 32 + nj * 8 + t4 * 2;
                    float p0 = exp2f(acc[mi][nj][hh * 2]);
                    float p1 = exp2f(acc[mi][nj][hh * 2 + 1]);
                    float2 o; o.x = p0; o.y = p1;
                    *(float2*)(Pg + (size_t)r * S_LEN + nt * 128 + cl) = o;
                    *(__half2*)(Ps + r * 136 + cl) = __floats2half2_rn(p0, p1);
                }
            }

        __syncthreads();     // Ps visible; V(nt) resident

        // ---- PV (ldmatrix frags) ----
        #pragma unroll
        for (int kg = 0; kg < 8; kg++) {
            uint32_t af[4], bf[2][4];
            ldm4(af, smem_u32(&Ps[(wr2 * 16 + l15) * 136 + kg * 16 + lhi * 8]));
            #pragma unroll
            for (int ng = 0; ng < 2; ng++)
                ldm4(bf[ng], smem_u32(&Vc[(wc2 * 32 + ng * 16 + brow) * 136 + kg * 16 + bcol8]));
            #pragma unroll
            for (int nj = 0; nj < 4; nj++) {
                int ng = nj >> 1, fo = (nj & 1) * 2;
                mma_fp16(accPV[nj], af, bf[ng][fo], bf[ng][fo + 1]);
            }
        }
        // no trailing sync: next tile's top sync protects buffer reuse
    }

    // ---- ctx write (fp16) ----
    #pragma unroll
    for (int nj = 0; nj < 4; nj++) {
        int col = h * 64 + wc2 * 32 + nj * 8 + t4 * 2;
        #pragma unroll
        for (int hh = 0; hh < 2; hh++) {
            int row = b * S_LEN + q0 + wr2 * 16 + g + hh * 8;
            *(__half2*)(g_ctx + (size_t)row * D_DIM + col) =
                __floats2half2_rn(accPV[nj][hh * 2], accPV[nj][hh * 2 + 1]);
        }
    }
}

// ---------------------------------------------------------------------------
extern "C" void kernel_launch(void* const* d_in, const int* in_sizes, int n_in,
                              void* d_out, int out_size)
{
    (void)in_sizes; (void)n_in; (void)out_size;

    const float* hidden = (const float*)d_in[0];
    const int*   mask   = (const int*)  d_in[1];
    const int*   stypes = (const int*)  d_in[2];
    const float* Wq = (const float*)d_in[3];
    const float* bq = (const float*)d_in[4];
    const float* Wk = (const float*)d_in[5];
    const float* bk = (const float*)d_in[6];
    const float* Wv = (const float*)d_in[7];
    const float* bv = (const float*)d_in[8];
    const float* Wo = (const float*)d_in[9];
    const float* bo = (const float*)d_in[10];
    const float* sw = (const float*)d_in[11];

    float* out   = (float*)d_out;
    float* probs = out + (size_t)M_ROWS * D_DIM;

    __half *hidp, *wtp;
    float *mbp;
    cudaGetSymbolAddress((void**)&hidp, g_hid);
    cudaGetSymbolAddress((void**)&wtp,  g_wt);
    cudaGetSymbolAddress((void**)&mbp,  g_mbias);

    cudaFuncSetAttribute(proj_qkv,   cudaFuncAttributeMaxDynamicSharedMemorySize, PJ_SMEM);
    cudaFuncSetAttribute(proj_o,     cudaFuncAttributeMaxDynamicSharedMemorySize, PJ_SMEM);
    cudaFuncSetAttribute(flash_fp16, cudaFuncAttributeMaxDynamicSharedMemorySize, FL_SMEM);

    prep_hid<<<2064, 256>>>((const float4*)hidden, (uint4*)hidp, 524288,
                            mask, mbp, 2 * S_LEN);
    prep_w<<<dim3(32, 32, 4), dim3(32, 8)>>>(Wq, Wk, Wv, Wo, wtp);

    proj_qkv<<<dim3(8, 32, 3), 256, PJ_SMEM>>>(bq, bk, bv, stypes, sw);

    flash_fp16<<<dim3(32, 32), 256, FL_SMEM>>>(probs);

    proj_o<<<dim3(8, 32), 256, PJ_SMEM>>>(bo, out);
}

// round 14
// speedup vs baseline: 2.0681x; 1.0468x over previous
#include <cuda_runtime.h>
#include <cuda_fp16.h>
#include <math_constants.h>
#include <cstdint>

#define S_LEN  2048
#define D_DIM  1024
#define N_H    16
#define M_ROWS 4096

// ------------------------- device scratch (bss) ----------------------------
#define DEVBUF __device__ __align__(256)
DEVBUF __half g_hid[M_ROWS * D_DIM];       // fp16, natural [row][k]
DEVBUF __half g_wt [4 * D_DIM * D_DIM];    // W^T [n][k] fp16
DEVBUF __half g_q  [M_ROWS * D_DIM];       // [token][1024]
DEVBUF __half g_k  [M_ROWS * D_DIM];
DEVBUF __half g_vt [32 * 64 * S_LEN];      // [bh][d][token]
DEVBUF __half g_ctx[M_ROWS * D_DIM];
DEVBUF float  g_mbias[2 * S_LEN];          // mask ? 0 : -1e30

// ------------------------------ helpers ------------------------------------
__device__ __forceinline__ uint32_t smem_u32(const void* p) {
    return (uint32_t)__cvta_generic_to_shared(p);
}
__device__ __forceinline__ void ldm4(uint32_t* r, uint32_t a) {
    asm volatile("ldmatrix.sync.aligned.m8n8.x4.shared.b16 {%0,%1,%2,%3}, [%4];"
                 : "=r"(r[0]), "=r"(r[1]), "=r"(r[2]), "=r"(r[3]) : "r"(a));
}
__device__ __forceinline__ void mma_fp16(float* c, const uint32_t* a,
                                         uint32_t b0, uint32_t b1) {
    asm volatile("mma.sync.aligned.m16n8k16.row.col.f32.f16.f16.f32 "
                 "{%0,%1,%2,%3}, {%4,%5,%6,%7}, {%8,%9}, {%0,%1,%2,%3};"
                 : "+f"(c[0]), "+f"(c[1]), "+f"(c[2]), "+f"(c[3])
                 : "r"(a[0]), "r"(a[1]), "r"(a[2]), "r"(a[3]), "r"(b0), "r"(b1));
}
__device__ __forceinline__ void cpa(void* d, const void* s) {
    asm volatile("cp.async.cg.shared.global [%0], [%1], 16;"
                 :: "r"(smem_u32(d)), "l"(s));
}
__device__ __forceinline__ void cp_commit() { asm volatile("cp.async.commit_group;"); }
template<int N> __device__ __forceinline__ void cp_wait() {
    asm volatile("cp.async.wait_group %0;" :: "n"(N));
}
__device__ __forceinline__ void stg_cs2(float* p, float x, float y) {
    asm volatile("st.global.cs.v2.f32 [%0], {%1, %2};"
                 :: "l"(p), "f"(x), "f"(y) : "memory");
}

// ---------------------------------------------------------------------------
// prep: fp32 -> fp16 hidden (+ mask bias); transpose + fp16 weights
// ---------------------------------------------------------------------------
__global__ __launch_bounds__(256)
void prep_hid(const float4* __restrict__ in, uint4* __restrict__ out, int ng,
              const int* __restrict__ mask, float* __restrict__ mbias, int nb)
{
    int i = blockIdx.x * 256 + threadIdx.x;
    if (i < ng) {
        float4 v0 = in[i * 2], v1 = in[i * 2 + 1];
        __half2 h0 = __floats2half2_rn(v0.x, v0.y);
        __half2 h1 = __floats2half2_rn(v0.z, v0.w);
        __half2 h2 = __floats2half2_rn(v1.x, v1.y);
        __half2 h3 = __floats2half2_rn(v1.z, v1.w);
        uint4 o;
        o.x = *(uint32_t*)&h0; o.y = *(uint32_t*)&h1;
        o.z = *(uint32_t*)&h2; o.w = *(uint32_t*)&h3;
        out[i] = o;
    }
    int j = i - ng;
    if (j >= 0 && j < nb) mbias[j] = mask[j] ? 0.f : -1e30f;
}

__global__ __launch_bounds__(256)
void prep_w(const float* __restrict__ W0, const float* __restrict__ W1,
            const float* __restrict__ W2, const float* __restrict__ W3,
            __half* __restrict__ outbase)
{
    __shared__ float tile[32][33];
    const int z = blockIdx.z;
    const float* W = (z == 0) ? W0 : (z == 1) ? W1 : (z == 2) ? W2 : W3;
    __half* out = outbase + (size_t)z * D_DIM * D_DIM;
    const int tx = threadIdx.x, ty = threadIdx.y;
    const int x = blockIdx.x * 32 + tx, y0 = blockIdx.y * 32;
    #pragma unroll
    for (int i = 0; i < 4; i++)
        tile[ty + i * 8][tx] = W[(size_t)(y0 + ty + i * 8) * D_DIM + x];
    __syncthreads();
    #pragma unroll
    for (int i = 0; i < 4; i++) {
        int n = blockIdx.x * 32 + ty + i * 8;
        int k = y0 + tx;
        out[(size_t)n * D_DIM + k] = __float2half_rn(tile[tx][ty + i * 8]);
    }
}

// ---------------------------------------------------------------------------
// fp16 projection GEMM: 128x128 tile, BK=64, 2-stage cp.async pipeline.
// Stage: A[128][72]h + B[128][72]h (pitch 144B) = 36864 B. 16 iterations.
// ---------------------------------------------------------------------------
#define PJ_B     18432
#define PJ_STG   36864
#define PJ_SMEM  (2 * PJ_STG)

__device__ __forceinline__ void proj_load(char* base, const __half* Ag,
                                          const __half* Bg, int bm, int bn,
                                          int k0, int t)
{
    #pragma unroll
    for (int j = 0; j < 4; j++) {
        int idx = j * 256 + t;
        int r = idx >> 3, c = idx & 7;
        cpa(base + r * 144 + c * 16,        Ag + (size_t)(bm + r) * D_DIM + k0 + c * 8);
        cpa(base + PJ_B + r * 144 + c * 16, Bg + (size_t)(bn + r) * D_DIM + k0 + c * 8);
    }
}

__device__ __forceinline__ void proj_mainloop(const __half* Ag, const __half* Bg,
                                              char* sm, int bm, int bn, int t,
                                              float acc[4][4][4])
{
    const int lane = t & 31, wid = t >> 5;
    const int wr = wid >> 2, wc = wid & 3;
    const int l15 = lane & 15, lhi = lane >> 4;
    const int brow = (lane & 7) + ((lane & 16) ? 8 : 0);
    const int bcol8 = (lane & 8) ? 8 : 0;

    proj_load(sm, Ag, Bg, bm, bn, 0, t);
    cp_commit();

    for (int c = 0; c < 16; c++) {
        if (c < 15) {
            proj_load(sm + ((c + 1) & 1) * PJ_STG, Ag, Bg, bm, bn, (c + 1) * 64, t);
            cp_commit();
            cp_wait<1>();
        } else {
            cp_wait<0>();
        }
        __syncthreads();
        const __half* A = (const __half*)(sm + (c & 1) * PJ_STG);
        const __half* B = (const __half*)(sm + (c & 1) * PJ_STG + PJ_B);
        #pragma unroll
        for (int kg = 0; kg < 4; kg++) {
            uint32_t af[4][4], bf[2][4];
            #pragma unroll
            for (int mi = 0; mi < 4; mi++)
                ldm4(af[mi], smem_u32(&A[(wr * 64 + mi * 16 + l15) * 72 + kg * 16 + lhi * 8]));
            #pragma unroll
            for (int ng = 0; ng < 2; ng++)
                ldm4(bf[ng], smem_u32(&B[(wc * 32 + ng * 16 + brow) * 72 + kg * 16 + bcol8]));
            #pragma unroll
            for (int mi = 0; mi < 4; mi++)
                #pragma unroll
                for (int nj = 0; nj < 4; nj++) {
                    int ng = nj >> 1, fo = (nj & 1) * 2;
                    mma_fp16(acc[mi][nj], af[mi], bf[ng][fo], bf[ng][fo + 1]);
                }
        }
        __syncthreads();
    }
}

__global__ __launch_bounds__(256, 2)
void proj_qkv(const float* __restrict__ bq, const float* __restrict__ bk,
              const float* __restrict__ bv, const int* __restrict__ stypes,
              const float* __restrict__ sw)
{
    extern __shared__ __align__(16) char sm[];
    const int t = threadIdx.x, lane = t & 31, wid = t >> 5;
    const int wr = wid >> 2, wc = wid & 3;
    const int g = lane >> 2, t4 = lane & 3;
    const int bm = blockIdx.y * 128, bn = blockIdx.x * 128;
    const int z = blockIdx.z;

    const float* bias = (z == 0) ? bq : (z == 1) ? bk : bv;
    const __half* Bg = g_wt + (size_t)z * D_DIM * D_DIM;

    float acc[4][4][4] = {};
    proj_mainloop(g_hid, Bg, sm, bm, bn, t, acc);

    const float QSCALE = 0.125f * 1.4426950408889634f;  // exp2 form
    #pragma unroll
    for (int mi = 0; mi < 4; mi++)
        #pragma unroll
        for (int nj = 0; nj < 4; nj++) {
            int col = bn + wc * 32 + nj * 8 + t4 * 2;
            float b0 = bias[col], b1 = bias[col + 1];
            #pragma unroll
            for (int hh = 0; hh < 2; hh++) {
                int row = bm + wr * 64 + mi * 16 + g + hh * 8;
                float s = 1.0f;
                if (z == 0) s = sw[stypes[row] * N_H + (col >> 6)] * QSCALE;
                float x = (acc[mi][nj][hh * 2]     + b0) * s;
                float y = (acc[mi][nj][hh * 2 + 1] + b1) * s;
                if (z < 2) {
                    __half* O = (z == 0) ? g_q : g_k;
                    *(__half2*)(O + (size_t)row * D_DIM + col) = __floats2half2_rn(x, y);
                } else {
                    int b = row >> 11, tok = row & 2047;
                    int hd = col >> 6, dl = col & 63;
                    size_t base = ((size_t)((b << 4) + hd) * 64 + dl) * S_LEN;
                    g_vt[base + tok]         = __float2half_rn(x);
                    g_vt[base + S_LEN + tok] = __float2half_rn(y);
                }
            }
        }
}

__global__ __launch_bounds__(256, 2)
void proj_o(const float* __restrict__ bias, float* __restrict__ Cf)
{
    extern __shared__ __align__(16) char sm[];
    const int t = threadIdx.x, lane = t & 31, wid = t >> 5;
    const int wr = wid >> 2, wc = wid & 3;
    const int g = lane >> 2, t4 = lane & 3;
    const int bm = blockIdx.y * 128, bn = blockIdx.x * 128;

    float acc[4][4][4] = {};
    proj_mainloop(g_ctx, g_wt + (size_t)3 * D_DIM * D_DIM, sm, bm, bn, t, acc);

    #pragma unroll
    for (int mi = 0; mi < 4; mi++)
        #pragma unroll
        for (int nj = 0; nj < 4; nj++) {
            int col = bn + wc * 32 + nj * 8 + t4 * 2;
            float b0 = bias[col], b1 = bias[col + 1];
            #pragma unroll
            for (int hh = 0; hh < 2; hh++) {
                int row = bm + wr * 64 + mi * 16 + g + hh * 8;
                float2 o;
                o.x = acc[mi][nj][hh * 2]     + b0;
                o.y = acc[mi][nj][hh * 2 + 1] + b1;
                *(float2*)(Cf + (size_t)row * D_DIM + col) = o;
            }
        }
}

// ---------------------------------------------------------------------------
// flash_fp16: BM=64 q rows, 256 threads, 2 CTAs/SM (R13 structure).
// probs written with st.global.cs (streaming, evict-first).
// ---------------------------------------------------------------------------
#define FL_K    0          // 2 x [128][72]h = 36864
#define FL_V    36864      // 2 x [64][136]h = 34816  (pass1: K buf2 here)
#define FL_PS   71680      // [64][136]h     = 17408  (stages Q [64][72]h)
#define FL_IL   89088      // float[64]
#define FL_MB   89344      // float[3][128]
#define FL_RED  90880      // float[4][64]
#define FL_SMEM 92160

__global__ __launch_bounds__(256, 2)
void flash_fp16(float* __restrict__ probs)
{
    extern __shared__ __align__(16) char sm[];
    const int t = threadIdx.x, lane = t & 31, wid = t >> 5;
    const int bh = blockIdx.y, b = bh >> 4, h = bh & 15;
    const int q0 = blockIdx.x * 64;
    const int g = lane >> 2, t4 = lane & 3;
    const int l15 = lane & 15, lhi = lane >> 4;
    const int brow = (lane & 7) + ((lane & 16) ? 8 : 0);
    const int bcol8 = (lane & 8) ? 8 : 0;

    __half* Ps  = (__half*)(sm + FL_PS);
    float* il   = (float*)(sm + FL_IL);
    float* mb   = (float*)(sm + FL_MB);
    float* red  = (float*)(sm + FL_RED);

    const int wr = wid >> 2, wc = wid & 3;     // QK: 32q x 32tok strips (wr 0..1)
    const int wr2 = wid >> 1, wc2 = wid & 1;   // PV: 16q x 32d strips  (wr2 0..3)

    const float* mbg = g_mbias + b * S_LEN;

    auto kb1 = [&](int i) -> char* {           // pass-1 triple K buffers
        return sm + (i == 2 ? FL_V : FL_K + i * 18432);
    };

    // preload group A: Q (staged in Ps, pitch 72h, 64 rows) + K(0) + mb(0)
    #pragma unroll
    for (int j = 0; j < 2; j++) {
        int idx = j * 256 + t;
        int r = idx >> 3, c = idx & 7;
        cpa((char*)Ps + r * 144 + c * 16,
            g_q + (size_t)(b * S_LEN + q0 + r) * D_DIM + h * 64 + c * 8);
    }
    #pragma unroll
    for (int j = 0; j < 4; j++) {
        int idx = j * 256 + t;
        int r = idx >> 3, c = idx & 7;
        cpa(kb1(0) + r * 144 + c * 16,
            g_k + (size_t)(b * S_LEN + r) * D_DIM + h * 64 + c * 8);
    }
    if (t < 32) cpa((char*)mb + t * 16, mbg + t * 4);
    cp_commit();
    // preload group B: K(1) + mb(1)
    #pragma unroll
    for (int j = 0; j < 4; j++) {
        int idx = j * 256 + t;
        int r = idx >> 3, c = idx & 7;
        cpa(kb1(1) + r * 144 + c * 16,
            g_k + (size_t)(b * S_LEN + 128 + r) * D_DIM + h * 64 + c * 8);
    }
    if (t < 32) cpa((char*)mb + 512 + t * 16, mbg + 128 + t * 4);
    cp_commit();

    cp_wait<1>();
    __syncthreads();

    // Q A-fragments -> registers
    uint32_t qf[4][2][4];
    {
        const __half* Qs = (const __half*)Ps;
        #pragma unroll
        for (int kg = 0; kg < 4; kg++)
            #pragma unroll
            for (int mi = 0; mi < 2; mi++)
                ldm4(qf[kg][mi],
                     smem_u32(&Qs[(wr * 32 + mi * 16 + l15) * 72 + kg * 16 + lhi * 8]));
    }

    float lp[2][2] = {};

    // =================== pass 1: row sums ===================
    for (int nt = 0; nt < 16; nt++) {
        if (nt > 0) {
            if (nt < 15) cp_wait<1>(); else cp_wait<0>();
            __syncthreads();
        }
        if (nt + 2 <= 15) {
            int dst = (nt + 2) % 3;
            #pragma unroll
            for (int j = 0; j < 4; j++) {
                int idx = j * 256 + t;
                int r = idx >> 3, c = idx & 7;
                cpa(kb1(dst) + r * 144 + c * 16,
                    g_k + (size_t)(b * S_LEN + (nt + 2) * 128 + r) * D_DIM + h * 64 + c * 8);
            }
            if (t < 32) cpa((char*)mb + dst * 512 + t * 16, mbg + (nt + 2) * 128 + t * 4);
            cp_commit();
        }

        const __half* K = (const __half*)kb1(nt % 3);
        const float* mbc = mb + (nt % 3) * 128;

        float acc[2][4][4];
        #pragma unroll
        for (int nj = 0; nj < 4; nj++) {
            int cl = wc * 32 + nj * 8 + t4 * 2;
            float m0 = mbc[cl], m1 = mbc[cl + 1];
            #pragma unroll
            for (int mi = 0; mi < 2; mi++) {
                acc[mi][nj][0] = m0; acc[mi][nj][1] = m1;
                acc[mi][nj][2] = m0; acc[mi][nj][3] = m1;
            }
        }
        #pragma unroll
        for (int kg = 0; kg < 4; kg++) {
            uint32_t bf[2][4];
            #pragma unroll
            for (int ng = 0; ng < 2; ng++)
                ldm4(bf[ng], smem_u32(&K[(wc * 32 + ng * 16 + brow) * 72 + kg * 16 + bcol8]));
            #pragma unroll
            for (int mi = 0; mi < 2; mi++)
                #pragma unroll
                for (int nj = 0; nj < 4; nj++) {
                    int ng = nj >> 1, fo = (nj & 1) * 2;
                    mma_fp16(acc[mi][nj], qf[kg][mi], bf[ng][fo], bf[ng][fo + 1]);
                }
        }

        #pragma unroll
        for (int mi = 0; mi < 2; mi++)
            #pragma unroll
            for (int hh = 0; hh < 2; hh++) {
                float s = 0.f;
                #pragma unroll
                for (int nj = 0; nj < 4; nj++)
                    s += exp2f(acc[mi][nj][hh * 2]) + exp2f(acc[mi][nj][hh * 2 + 1]);
                s += __shfl_xor_sync(0xffffffffu, s, 1);
                s += __shfl_xor_sync(0xffffffffu, s, 2);
                lp[mi][hh] += s;
            }
    }

    if (t4 == 0)
        #pragma unroll
        for (int mi = 0; mi < 2; mi++)
            #pragma unroll
            for (int hh = 0; hh < 2; hh++)
                red[wc * 64 + wr * 32 + mi * 16 + g + hh * 8] = lp[mi][hh];
    __syncthreads();
    if (t < 64)
        il[t] = -__log2f(red[t] + red[64 + t] + red[128 + t] + red[192 + t]);

    // preload pass 2: ONE group = K(0) + mb(0) + V(0)
    #pragma unroll
    for (int j = 0; j < 4; j++) {
        int idx = j * 256 + t;
        int r = idx >> 3, c = idx & 7;
        cpa(sm + FL_K + r * 144 + c * 16,
            g_k + (size_t)(b * S_LEN + r) * D_DIM + h * 64 + c * 8);
    }
    if (t < 32) cpa((char*)mb + t * 16, mbg + t * 4);
    #pragma unroll
    for (int j = 0; j < 4; j++) {
        int idx = j * 256 + t;
        int r = idx >> 4, c = idx & 15;
        cpa(sm + FL_V + r * 272 + c * 16,
            g_vt + ((size_t)bh * 64 + r) * S_LEN + c * 8);
    }
    cp_commit();

    // =================== pass 2: emit probs + PV ===================
    float accPV[4][4] = {};
    float* Pg = probs + ((size_t)bh * S_LEN + q0) * S_LEN;

    for (int nt = 0; nt < 16; nt++) {
        cp_wait<0>();
        __syncthreads();

        if (nt < 15) {
            #pragma unroll
            for (int j = 0; j < 4; j++) {
                int idx = j * 256 + t;
                int r = idx >> 3, c = idx & 7;
                cpa(sm + FL_K + ((nt + 1) & 1) * 18432 + r * 144 + c * 16,
                    g_k + (size_t)(b * S_LEN + (nt + 1) * 128 + r) * D_DIM + h * 64 + c * 8);
            }
            if (t < 32) cpa((char*)mb + ((nt + 1) & 1) * 512 + t * 16,
                            mbg + (nt + 1) * 128 + t * 4);
            #pragma unroll
            for (int j = 0; j < 4; j++) {
                int idx = j * 256 + t;
                int r = idx >> 4, c = idx & 15;
                cpa(sm + FL_V + ((nt + 1) & 1) * 17408 + r * 272 + c * 16,
                    g_vt + ((size_t)bh * 64 + r) * S_LEN + (nt + 1) * 128 + c * 8);
            }
            cp_commit();
        }

        const __half* K   = (const __half*)(sm + FL_K + (nt & 1) * 18432);
        const __half* Vc  = (const __half*)(sm + FL_V + (nt & 1) * 17408);
        const float* mbc  = mb + (nt & 1) * 128;

        float lr[2][2];
        #pragma unroll
        for (int mi = 0; mi < 2; mi++)
            #pragma unroll
            for (int hh = 0; hh < 2; hh++)
                lr[mi][hh] = il[wr * 32 + mi * 16 + g + hh * 8];

        float acc[2][4][4];
        #pragma unroll
        for (int nj = 0; nj < 4; nj++) {
            int cl = wc * 32 + nj * 8 + t4 * 2;
            float m0 = mbc[cl], m1 = mbc[cl + 1];
            #pragma unroll
            for (int mi = 0; mi < 2; mi++) {
                acc[mi][nj][0] = m0 + lr[mi][0];
                acc[mi][nj][1] = m1 + lr[mi][0];
                acc[mi][nj][2] = m0 + lr[mi][1];
                acc[mi][nj][3] = m1 + lr[mi][1];
            }
        }
        #pragma unroll
        for (int kg = 0; kg < 4; kg++) {
            uint32_t bf[2][4];
            #pragma unroll
            for (int ng = 0; ng < 2; ng++)
                ldm4(bf[ng], smem_u32(&K[(wc * 32 + ng * 16 + brow) * 72 + kg * 16 + bcol8]));
            #pragma unroll
            for (int mi = 0; mi < 2; mi++)
                #pragma unroll
                for (int nj = 0; nj < 4; nj++) {
                    int ng = nj >> 1, fo = (nj & 1) * 2;
                    mma_fp16(acc[mi][nj], qf[kg][mi], bf[ng][fo], bf[ng][fo + 1]);
                }
        }

        // p = exp2(acc): streaming-write fp32 probs, fp16 to Ps
        #pragma unroll
        for (int mi = 0; mi < 2; mi++)
            #pragma unroll
            for (int hh = 0; hh < 2; hh++) {
                int r = wr * 32 + mi * 16 + g + hh * 8;
                #pragma unroll
                for (int nj = 0; nj < 4; nj++) {
                    int cl = wc * 32 + nj * 8 + t4 * 2;
                    float p0 = exp2f(acc[mi][nj][hh * 2]);
                    float p1 = exp2f(acc[mi][nj][hh * 2 + 1]);
                    stg_cs2(Pg + (size_t)r * S_LEN + nt * 128 + cl, p0, p1);
                    *(__half2*)(Ps + r * 136 + cl) = __floats2half2_rn(p0, p1);
                }
            }

        __syncthreads();     // Ps visible; V(nt) resident

        // ---- PV (ldmatrix frags) ----
        #pragma unroll
        for (int kg = 0; kg < 8; kg++) {
            uint32_t af[4], bf[2][4];
            ldm4(af, smem_u32(&Ps[(wr2 * 16 + l15) * 136 + kg * 16 + lhi * 8]));
            #pragma unroll
            for (int ng = 0; ng < 2; ng++)
                ldm4(bf[ng], smem_u32(&Vc[(wc2 * 32 + ng * 16 + brow) * 136 + kg * 16 + bcol8]));
            #pragma unroll
            for (int nj = 0; nj < 4; nj++) {
                int ng = nj >> 1, fo = (nj & 1) * 2;
                mma_fp16(accPV[nj], af, bf[ng][fo], bf[ng][fo + 1]);
            }
        }
        // no trailing sync: next tile's top sync protects buffer reuse
    }

    // ---- ctx write (fp16) ----
    #pragma unroll
    for (int nj = 0; nj < 4; nj++) {
        int col = h * 64 + wc2 * 32 + nj * 8 + t4 * 2;
        #pragma unroll
        for (int hh = 0; hh < 2; hh++) {
            int row = b * S_LEN + q0 + wr2 * 16 + g + hh * 8;
            *(__half2*)(g_ctx + (size_t)row * D_DIM + col) =
                __floats2half2_rn(accPV[nj][hh * 2], accPV[nj][hh * 2 + 1]);
        }
    }
}

// ---------------------------------------------------------------------------
extern "C" void kernel_launch(void* const* d_in, const int* in_sizes, int n_in,
                              void* d_out, int out_size)
{
    (void)in_sizes; (void)n_in; (void)out_size;

    const float* hidden = (const float*)d_in[0];
    const int*   mask   = (const int*)  d_in[1];
    const int*   stypes = (const int*)  d_in[2];
    const float* Wq = (const float*)d_in[3];
    const float* bq = (const float*)d_in[4];
    const float* Wk = (const float*)d_in[5];
    const float* bk = (const float*)d_in[6];
    const float* Wv = (const float*)d_in[7];
    const float* bv = (const float*)d_in[8];
    const float* Wo = (const float*)d_in[9];
    const float* bo = (const float*)d_in[10];
    const float* sw = (const float*)d_in[11];

    float* out   = (float*)d_out;
    float* probs = out + (size_t)M_ROWS * D_DIM;

    __half *hidp, *wtp;
    float *mbp;
    cudaGetSymbolAddress((void**)&hidp, g_hid);
    cudaGetSymbolAddress((void**)&wtp,  g_wt);
    cudaGetSymbolAddress((void**)&mbp,  g_mbias);

    cudaFuncSetAttribute(proj_qkv,   cudaFuncAttributeMaxDynamicSharedMemorySize, PJ_SMEM);
    cudaFuncSetAttribute(proj_o,     cudaFuncAttributeMaxDynamicSharedMemorySize, PJ_SMEM);
    cudaFuncSetAttribute(flash_fp16, cudaFuncAttributeMaxDynamicSharedMemorySize, FL_SMEM);

    prep_hid<<<2064, 256>>>((const float4*)hidden, (uint4*)hidp, 524288,
                            mask, mbp, 2 * S_LEN);
    prep_w<<<dim3(32, 32, 4), dim3(32, 8)>>>(Wq, Wk, Wv, Wo, wtp);

    proj_qkv<<<dim3(8, 32, 3), 256, PJ_SMEM>>>(bq, bk, bv, stypes, sw);

    flash_fp16<<<dim3(32, 32), 256, FL_SMEM>>>(probs);

    proj_o<<<dim3(8, 32), 256, PJ_SMEM>>>(bo, out);
}